// round 10
// baseline (speedup 1.0000x reference)
#include <cuda_runtime.h>
#include <cuda_bf16.h>
#include <mma.h>
#include <cstdint>

using namespace nvcuda;

// ---------------- problem constants ----------------
#define BB   32
#define CC_  384
#define HH_  56
#define WW_  56
#define NS   3136        // H*W
#define MR   100352      // B*N  (divisible by 256)
#define HID  1536
#define NHEADS 8
#define HD   48
#define GG   7           // grid size
#define SSZ  8           // sparse size
#define NWIN 1568        // B*GG*GG
#define EPSV 1e-5f

// ---------------- scratch (device globals; allocation-free) ----------------
__device__ __align__(16) float          g_xT [(size_t)MR * CC_];       // [B,N,C] fp32
__device__ __align__(16) __nv_bfloat16  g_hln[(size_t)MR * CC_];       // LN1 out, window-major
__device__ __align__(16) __nv_bfloat16  g_qkv[(size_t)MR * 3 * CC_];   // window-major
__device__ __align__(16) __nv_bfloat16  g_o  [(size_t)MR * CC_];       // attn out, window-major
__device__ __align__(16) float          g_x1 [(size_t)MR * CC_];       // residual1, token-major
__device__ __align__(16) __nv_bfloat16  g_ln2[(size_t)MR * CC_];       // token-major
__device__ __align__(16) __nv_bfloat16  g_m1 [(size_t)MR * HID];       // fc1 out
__device__ __align__(16) __nv_bfloat16  g_mg [(size_t)MR * HID];       // dwconv+gelu out
// bf16 weights, SAME [K, N] layout as the fp32 originals
__device__ __align__(16) __nv_bfloat16  g_wq[(size_t)384 * 1152];
__device__ __align__(16) __nv_bfloat16  g_wp[(size_t)384 * 384];
__device__ __align__(16) __nv_bfloat16  g_w1[(size_t)384 * 1536];
__device__ __align__(16) __nv_bfloat16  g_w2[(size_t)1536 * 384];

// ---------------- K0: ALL weight fp32 -> bf16 converts in ONE kernel ----------------
__global__ void k_wprep_all(const float* __restrict__ qkv_w, const float* __restrict__ proj_w,
                            const float* __restrict__ fc1_w, const float* __restrict__ fc2_w) {
    size_t i = ((size_t)blockIdx.x * 256 + threadIdx.x) * 4;
    const float* src; __nv_bfloat16* dst; size_t off;
    if (i < 442368)        { src = qkv_w;  dst = g_wq; off = i; }
    else if (i < 589824)   { src = proj_w; dst = g_wp; off = i - 442368; }
    else if (i < 1179648)  { src = fc1_w;  dst = g_w1; off = i - 589824; }
    else if (i < 1769472)  { src = fc2_w;  dst = g_w2; off = i - 1179648; }
    else return;
    float4 f = *(const float4*)&src[off];
    __nv_bfloat162 lo = __floats2bfloat162_rn(f.x, f.y);
    __nv_bfloat162 hi = __floats2bfloat162_rn(f.z, f.w);
    *(uint2*)&dst[off] = make_uint2(*(uint32_t*)&lo, *(uint32_t*)&hi);
}

// ---------------- K1: NCHW -> [B,N,C] transpose ----------------
__global__ void k_transpose(const float* __restrict__ x) {
    __shared__ float tile[32][33];
    int b  = blockIdx.z;
    int n0 = blockIdx.x * 32, c0 = blockIdx.y * 32;
    const float* in  = x    + (size_t)b * CC_ * NS;
    float*       out = g_xT + (size_t)b * NS * CC_;
    int tx = threadIdx.x, ty = threadIdx.y;  // (32,8)
#pragma unroll
    for (int i = 0; i < 32; i += 8)
        tile[ty + i][tx] = in[(size_t)(c0 + ty + i) * NS + n0 + tx];
    __syncthreads();
#pragma unroll
    for (int i = 0; i < 32; i += 8)
        out[(size_t)(n0 + ty + i) * CC_ + c0 + tx] = tile[tx][ty + i];
}

// ---------------- K2/K6: LayerNorm (MODE 0: LN1 + window gather, MODE 1: LN2) ----------------
template<int MODE>
__global__ void k_layernorm(const float* __restrict__ gam, const float* __restrict__ bet) {
    int r   = blockIdx.x;
    int tid = threadIdx.x;          // 128
    const float* src = (MODE == 0 ? g_xT : g_x1) + (size_t)r * CC_;
    float v0 = src[tid], v1 = src[tid + 128], v2 = src[tid + 256];
    float s  = v0 + v1 + v2;
    float sq = v0 * v0 + v1 * v1 + v2 * v2;
#pragma unroll
    for (int o = 16; o; o >>= 1) {
        s  += __shfl_xor_sync(0xffffffffu, s,  o);
        sq += __shfl_xor_sync(0xffffffffu, sq, o);
    }
    __shared__ float ws[4], wq[4];
    int w = tid >> 5, l = tid & 31;
    if (l == 0) { ws[w] = s; wq[w] = sq; }
    __syncthreads();
    float mean = (ws[0] + ws[1] + ws[2] + ws[3]) * (1.0f / CC_);
    float var  = (wq[0] + wq[1] + wq[2] + wq[3]) * (1.0f / CC_) - mean * mean;
    float rstd = rsqrtf(var + EPSV);

    size_t orow;
    if (MODE == 0) {
        int b = r / NS, n = r % NS;
        int h = n / WW_, wpos = n % WW_;
        int gi = h % GG,    si = h / GG;
        int gj = wpos % GG, sj = wpos / GG;
        int win = (b * GG + gi) * GG + gj;
        int t   = si * SSZ + sj;
        orow = (size_t)win * 64 + t;
    } else {
        orow = (size_t)r;
    }
    __nv_bfloat16* dst = (MODE == 0 ? g_hln : g_ln2) + orow * CC_;
    dst[tid]       = __float2bfloat16((v0 - mean) * rstd * gam[tid]       + bet[tid]);
    dst[tid + 128] = __float2bfloat16((v1 - mean) * rstd * gam[tid + 128] + bet[tid + 128]);
    dst[tid + 256] = __float2bfloat16((v2 - mean) * rstd * gam[tid + 256] + bet[tid + 256]);
}

// ---------------- wmma GEMM, 256x128 CTA tile, 64x64 warp tile, K-tile 32, 3-stage ----------------
// 8 warps in 4(M) x 2(N); warp (wm,wn) computes rows [wm*64,+64) x cols [wn*64,+64).
// Fragment traffic: 8 ldsm-frags per 16 MMAs (was 6 per 8) -> 1.5x less L1 traffic per FLOP.
// dynamic smem: 3 x (A 256x40x2 = 20480 + B 32x136x2 = 8704) = 87552 B; epilogue aliases stage 0.
// MODE 0: QKV   A=g_hln  K=384  N=1152 -> g_qkv (bf16)
// MODE 1: PROJ  A=g_o    K=384  N=384  -> g_x1 = xT + gamma1*(A@W + b)  (window->token scatter)
// MODE 2: FC1   A=g_ln2  K=384  N=1536 -> g_m1 = bf16(A@W + b)
// MODE 3: FC2   A=g_mg   K=1536 N=384  -> out[b,c,n] = x1 + gamma2*(A@W + b)  (NCHW permute)
#define STG_BYTES 29184
#define GEMM_DSMEM (3 * STG_BYTES)

__device__ __forceinline__ uint32_t sptr(const void* p) {
    uint32_t a;
    asm("{ .reg .u64 t; cvta.to.shared.u64 t, %1; cvt.u32.u64 %0, t; }" : "=r"(a) : "l"(p));
    return a;
}

template<int MODE>
__global__ void __launch_bounds__(256, 1) k_gemm(
    const float* __restrict__ bias, const float* __restrict__ gamma,
    float* __restrict__ outp)
{
    constexpr int Kdim  = (MODE == 3) ? 1536 : 384;
    constexpr int Ncols = (MODE == 0) ? 1152 : ((MODE == 2) ? 1536 : 384);
    constexpr int NKT   = Kdim / 32;

    const __nv_bfloat16* A  = (MODE == 0) ? g_hln : (MODE == 1) ? g_o : (MODE == 2) ? g_ln2 : g_mg;
    const __nv_bfloat16* Bw = (MODE == 0) ? g_wq  : (MODE == 1) ? g_wp : (MODE == 2) ? g_w1 : g_w2;

    extern __shared__ __align__(16) char dsm[];

    int n0 = blockIdx.x * 128;
    int m0 = blockIdx.y * 256;
    int tid  = threadIdx.x;
    int warp = tid >> 5, lane = tid & 31;
    int wm = warp & 3, wn = warp >> 2;   // warp tile: rows [wm*64,+64), cols [wn*64,+64)

    wmma::fragment<wmma::accumulator, 16, 16, 16, float> acc[4][4];
#pragma unroll
    for (int i = 0; i < 4; i++)
#pragma unroll
        for (int j = 0; j < 4; j++) wmma::fill_fragment(acc[i][j], 0.0f);

    // stage s: A at dsm + s*STG (256 rows x 40 elems), B at +20480 (32 rows x 136 elems)
    auto load_stage = [&](int kt, int buf) {
        int k0 = kt * 32;
        char* st = dsm + buf * STG_BYTES;
#pragma unroll
        for (int s = 0; s < 6; s++) {
            int i = tid + s * 256;
            uint32_t dst; const __nv_bfloat16* src;
            if (i < 1024) {          // A: 256 rows x 4 chunks of 16B
                int r = i >> 2, c = i & 3;
                dst = sptr(st + (r * 40 + c * 8) * 2);
                src = A + (size_t)(m0 + r) * Kdim + k0 + c * 8;
            } else {                 // B: 32 rows x 16 chunks of 16B
                int j = i - 1024, r = j >> 4, c = j & 15;
                dst = sptr(st + 20480 + (r * 136 + c * 8) * 2);
                src = Bw + (size_t)(k0 + r) * Ncols + n0 + c * 8;
            }
            asm volatile("cp.async.cg.shared.global [%0], [%1], 16;" :: "r"(dst), "l"(src));
        }
        asm volatile("cp.async.commit_group;" ::: "memory");
    };

    load_stage(0, 0);
    load_stage(1, 1);

    for (int kt = 0; kt < NKT; ++kt) {
        asm volatile("cp.async.wait_group 1;" ::: "memory");   // group kt complete
        __syncthreads();                                       // data visible; frees buf (kt+2)%3
        int nb = kt + 2;
        if (nb < NKT) load_stage(nb, nb % 3);
        else asm volatile("cp.async.commit_group;" ::: "memory");  // uniform group count

        const __nv_bfloat16* cA = (const __nv_bfloat16*)(dsm + (kt % 3) * STG_BYTES);
        const __nv_bfloat16* cB = (const __nv_bfloat16*)(dsm + (kt % 3) * STG_BYTES + 20480);
#pragma unroll
        for (int ks = 0; ks < 32; ks += 16) {
            wmma::fragment<wmma::matrix_a, 16, 16, 16, __nv_bfloat16, wmma::row_major> af[4];
            wmma::fragment<wmma::matrix_b, 16, 16, 16, __nv_bfloat16, wmma::row_major> bf[4];
#pragma unroll
            for (int i = 0; i < 4; i++)
                wmma::load_matrix_sync(af[i], &cA[(wm * 64 + i * 16) * 40 + ks], 40);
#pragma unroll
            for (int j = 0; j < 4; j++)
                wmma::load_matrix_sync(bf[j], &cB[ks * 136 + wn * 64 + j * 16], 136);
#pragma unroll
            for (int i = 0; i < 4; i++)
#pragma unroll
                for (int j = 0; j < 4; j++)
                    wmma::mma_sync(acc[i][j], af[i], bf[j], acc[i][j]);
        }
    }
    __syncthreads();   // all compute done before aliasing stage smem for epilogue

    float* sEpi = (float*)dsm + warp * 320;   // 8 warps x 16x20 floats = 10240 B (fits A region)

#pragma unroll
    for (int i = 0; i < 4; i++) {
#pragma unroll
        for (int j = 0; j < 4; j++) {
            wmma::store_matrix_sync(sEpi, acc[i][j], 20, wmma::mem_row_major);
            __syncwarp();
            int growb = m0 + wm * 64 + i * 16;
            int gcolb = n0 + wn * 64 + j * 16;
#pragma unroll
            for (int e = 0; e < 8; e++) {
                int idx = e * 32 + lane;
                int rr, cc;
                if (MODE == 3) { cc = idx >> 4; rr = idx & 15; }     // column-major: coalesced over n
                else           { rr = idx >> 4; cc = idx & 15; }
                float v = sEpi[rr * 20 + cc];
                int grow = growb + rr, gcol = gcolb + cc;
                if (MODE == 0) {
                    g_qkv[(size_t)grow * Ncols + gcol] = __float2bfloat16(v);
                } else if (MODE == 2) {
                    g_m1[(size_t)grow * Ncols + gcol] = __float2bfloat16(v + bias[gcol]);
                } else if (MODE == 1) {
                    int win = grow >> 6, t = grow & 63;
                    int b = win / 49, wi = win % 49;
                    int gi = wi / 7, gj = wi % 7;
                    int si = t >> 3, sj = t & 7;
                    int h = si * GG + gi, wp = sj * GG + gj;
                    size_t ridx = ((size_t)b * NS + h * WW_ + wp) * CC_ + gcol;
                    g_x1[ridx] = g_xT[ridx] + gamma[gcol] * (v + bias[gcol]);
                } else {  // MODE 3
                    int b = grow / NS, n = grow % NS;
                    float ov = g_x1[(size_t)grow * CC_ + gcol]
                             + gamma[gcol] * (v + bias[gcol]);
                    outp[((size_t)b * CC_ + gcol) * NS + n] = ov;
                }
            }
            __syncwarp();
        }
    }
}

// ---------------- K4: attention, one block per (window, head), 4 warps ----------------
__global__ void __launch_bounds__(128) k_attn() {
    int win  = blockIdx.x;
    int head = blockIdx.y;
    __shared__ __nv_bfloat16 sq[64 * 56], sk[64 * 56], sv[64 * 56];
    __shared__ float sS[64 * 68];
    __shared__ __nv_bfloat16 sP[64 * 72];
    __shared__ float red[128];
    int tid = threadIdx.x;

    size_t base = (size_t)win * 64 * 1152;
#pragma unroll
    for (int m = 0; m < 3; m++) {
        const __nv_bfloat16* src = g_qkv + base + m * 384 + head * 48;
        __nv_bfloat16* dst = (m == 0) ? sq : (m == 1) ? sk : sv;
        for (int li = tid; li < 64 * 6; li += 128) {
            int t = li / 6, dg = (li % 6) * 8;
            *(uint4*)&dst[t * 56 + dg] = *(const uint4*)&src[(size_t)t * 1152 + dg];
        }
    }
    __syncthreads();

    int warp = tid >> 5;
    int m0 = warp * 16;
    {   // S = q @ k^T   [64x64], K=48
        wmma::fragment<wmma::accumulator, 16, 16, 16, float> acc[4];
#pragma unroll
        for (int j = 0; j < 4; j++) wmma::fill_fragment(acc[j], 0.0f);
#pragma unroll
        for (int k = 0; k < 48; k += 16) {
            wmma::fragment<wmma::matrix_a, 16, 16, 16, __nv_bfloat16, wmma::row_major> af;
            wmma::load_matrix_sync(af, &sq[m0 * 56 + k], 56);
#pragma unroll
            for (int j = 0; j < 4; j++) {
                wmma::fragment<wmma::matrix_b, 16, 16, 16, __nv_bfloat16, wmma::col_major> bf;
                wmma::load_matrix_sync(bf, &sk[(j * 16) * 56 + k], 56);
                wmma::mma_sync(acc[j], af, bf, acc[j]);
            }
        }
#pragma unroll
        for (int j = 0; j < 4; j++)
            wmma::store_matrix_sync(&sS[m0 * 68 + j * 16], acc[j], 68, wmma::mem_row_major);
    }
    __syncthreads();

    {   // softmax: 128 threads, 2 per row (each handles 32 cols), smem combine
        const float scale = 0.14433756729740643f;  // 48^-0.5
        int row = tid & 63, half = tid >> 6;
        const float* Srow = &sS[row * 68 + half * 32];
        float buf[32];
        float mx = -1e30f;
#pragma unroll
        for (int j = 0; j < 32; j++) { buf[j] = Srow[j] * scale; mx = fmaxf(mx, buf[j]); }
        red[tid] = mx;
        __syncthreads();
        mx = fmaxf(red[row], red[row + 64]);
        float sum = 0.0f;
#pragma unroll
        for (int j = 0; j < 32; j++) { buf[j] = __expf(buf[j] - mx); sum += buf[j]; }
        __syncthreads();
        red[tid] = sum;
        __syncthreads();
        float inv = 1.0f / (red[row] + red[row + 64]);
        __nv_bfloat16* Prow = &sP[row * 72 + half * 32];
#pragma unroll
        for (int j = 0; j < 32; j++) Prow[j] = __float2bfloat16(buf[j] * inv);
    }
    __syncthreads();

    {   // O = P @ V   [64x48], K=64
        wmma::fragment<wmma::accumulator, 16, 16, 16, float> acc[3];
#pragma unroll
        for (int j = 0; j < 3; j++) wmma::fill_fragment(acc[j], 0.0f);
#pragma unroll
        for (int k = 0; k < 64; k += 16) {
            wmma::fragment<wmma::matrix_a, 16, 16, 16, __nv_bfloat16, wmma::row_major> af;
            wmma::load_matrix_sync(af, &sP[m0 * 72 + k], 72);
#pragma unroll
            for (int j = 0; j < 3; j++) {
                wmma::fragment<wmma::matrix_b, 16, 16, 16, __nv_bfloat16, wmma::row_major> bf;
                wmma::load_matrix_sync(bf, &sv[k * 56 + j * 16], 56);
                wmma::mma_sync(acc[j], af, bf, acc[j]);
            }
        }
#pragma unroll
        for (int j = 0; j < 3; j++)
            wmma::store_matrix_sync(&sS[m0 * 68 + j * 16], acc[j], 68, wmma::mem_row_major);
    }
    __syncthreads();

    __nv_bfloat16* dst = g_o + (size_t)win * 64 * 384 + head * 48;
    for (int li = tid; li < 64 * 48; li += 128) {
        int t = li / 48, d = li % 48;
        dst[(size_t)t * 384 + d] = __float2bfloat16(sS[t * 68 + d]);
    }
}

// ---------------- K8: depthwise 3x3 conv + bias + exact GELU (4 rows/block) ----------------
__global__ void __launch_bounds__(256) k_dwconv(const float* __restrict__ wgt,
                                                const float* __restrict__ bias) {
    __shared__ __nv_bfloat16 s[6 * 58 * 64];   // 6 input rows x 58 w x 64 chans
    int b = blockIdx.y, h0 = blockIdx.x * 4;   // grid (14, 32)
    int tid = threadIdx.x;
    int c = tid & 63, sub = tid >> 6;          // sub = 0..3: output row within group

    for (int cc = 0; cc < HID; cc += 64) {
        __syncthreads();
        for (int li = tid; li < 6 * 58 * 8; li += 256) {
            int hr = li / 464;          // 0..5 -> input row h0-1+hr
            int rem = li % 464;
            int wi = rem >> 3;          // 0..57
            int grp = (rem & 7) * 8;
            int hh = h0 - 1 + hr, ww = wi - 1;
            uint4 val = make_uint4(0u, 0u, 0u, 0u);
            if (hh >= 0 && hh < HH_ && ww >= 0 && ww < WW_)
                val = *(const uint4*)&g_m1[((size_t)b * NS + hh * WW_ + ww) * HID + cc + grp];
            *(uint4*)&s[(hr * 58 + wi) * 64 + grp] = val;
        }
        __syncthreads();

        int ch = cc + c;
        float w9[9];
#pragma unroll
        for (int i = 0; i < 9; i++) w9[i] = wgt[ch * 9 + i];
        float bv = bias[ch];
        int h = h0 + sub;
        for (int w0 = 0; w0 < WW_; w0++) {
            float acc = bv;
#pragma unroll
            for (int dy = 0; dy < 3; dy++)
#pragma unroll
                for (int dx = 0; dx < 3; dx++)
                    acc += __bfloat162float(s[((sub + dy) * 58 + w0 + dx) * 64 + c]) * w9[dy * 3 + dx];
            float gl = 0.5f * acc * (1.0f + erff(acc * 0.70710678118f));
            g_mg[((size_t)b * NS + h * WW_ + w0) * HID + ch] = __float2bfloat16(gl);
        }
    }
}

// ---------------- launch ----------------
extern "C" void kernel_launch(void* const* d_in, const int* in_sizes, int n_in,
                              void* d_out, int out_size) {
    (void)in_sizes; (void)n_in; (void)out_size;
    const float* x      = (const float*)d_in[0];
    const float* ln1_g  = (const float*)d_in[1];
    const float* ln1_b  = (const float*)d_in[2];
    const float* qkv_w  = (const float*)d_in[3];
    const float* proj_w = (const float*)d_in[4];
    const float* proj_b = (const float*)d_in[5];
    const float* ln2_g  = (const float*)d_in[6];
    const float* ln2_b  = (const float*)d_in[7];
    const float* fc1_w  = (const float*)d_in[8];
    const float* fc1_b  = (const float*)d_in[9];
    const float* dw_w   = (const float*)d_in[10];
    const float* dw_b   = (const float*)d_in[11];
    const float* fc2_w  = (const float*)d_in[12];
    const float* fc2_b  = (const float*)d_in[13];
    const float* gamma1 = (const float*)d_in[14];
    const float* gamma2 = (const float*)d_in[15];
    float* out = (float*)d_out;

    // idempotent, deterministic, capture-safe
    cudaFuncSetAttribute(k_gemm<0>, cudaFuncAttributeMaxDynamicSharedMemorySize, GEMM_DSMEM);
    cudaFuncSetAttribute(k_gemm<1>, cudaFuncAttributeMaxDynamicSharedMemorySize, GEMM_DSMEM);
    cudaFuncSetAttribute(k_gemm<2>, cudaFuncAttributeMaxDynamicSharedMemorySize, GEMM_DSMEM);
    cudaFuncSetAttribute(k_gemm<3>, cudaFuncAttributeMaxDynamicSharedMemorySize, GEMM_DSMEM);

    k_wprep_all<<<1728, 256>>>(qkv_w, proj_w, fc1_w, fc2_w);                       // launch 0
    k_transpose<<<dim3(NS / 32, CC_ / 32, BB), dim3(32, 8)>>>(x);                  // launch 1
    k_layernorm<0><<<MR, 128>>>(ln1_g, ln1_b);                                     // launch 2
    k_gemm<0><<<dim3(1152 / 128, MR / 256), 256, GEMM_DSMEM>>>(nullptr, nullptr, nullptr); // 3
    k_attn<<<dim3(NWIN, NHEADS), 128>>>();                                         // launch 4
    k_gemm<1><<<dim3(384 / 128, MR / 256), 256, GEMM_DSMEM>>>(proj_b, gamma1, nullptr);    // 5 <- ncu
    k_layernorm<1><<<MR, 128>>>(ln2_g, ln2_b);
    k_gemm<2><<<dim3(1536 / 128, MR / 256), 256, GEMM_DSMEM>>>(fc1_b, nullptr, nullptr);
    k_dwconv<<<dim3(14, BB), 256>>>(dw_w, dw_b);
    k_gemm<3><<<dim3(384 / 128, MR / 256), 256, GEMM_DSMEM>>>(fc2_b, gamma2, out);
}

// round 12
// speedup vs baseline: 1.1257x; 1.1257x over previous
#include <cuda_runtime.h>
#include <cuda_bf16.h>
#include <mma.h>
#include <cstdint>

using namespace nvcuda;

// ---------------- problem constants ----------------
#define BB   32
#define CC_  384
#define HH_  56
#define WW_  56
#define NS   3136        // H*W
#define MR   100352      // B*N
#define HID  1536
#define NHEADS 8
#define HD   48
#define GG   7           // grid size
#define SSZ  8           // sparse size
#define NWIN 1568        // B*GG*GG
#define EPSV 1e-5f

// ---------------- scratch (device globals; allocation-free) ----------------
__device__ __align__(16) float          g_xT [(size_t)MR * CC_];       // [B,N,C] fp32
__device__ __align__(16) __nv_bfloat16  g_hln[(size_t)MR * CC_];       // LN1 out, window-major
__device__ __align__(16) __nv_bfloat16  g_qkv[(size_t)MR * 3 * CC_];   // window-major
__device__ __align__(16) __nv_bfloat16  g_o  [(size_t)MR * CC_];       // attn out, window-major
__device__ __align__(16) float          g_x1 [(size_t)MR * CC_];       // residual1, token-major
__device__ __align__(16) __nv_bfloat16  g_ln2[(size_t)MR * CC_];       // token-major
__device__ __align__(16) __nv_bfloat16  g_m1 [(size_t)MR * HID];       // fc1 out
__device__ __align__(16) __nv_bfloat16  g_mg [(size_t)MR * HID];       // dwconv+gelu out
// bf16 weights, SAME [K, N] layout as the fp32 originals
__device__ __align__(16) __nv_bfloat16  g_wq[(size_t)384 * 1152];
__device__ __align__(16) __nv_bfloat16  g_wp[(size_t)384 * 384];
__device__ __align__(16) __nv_bfloat16  g_w1[(size_t)384 * 1536];
__device__ __align__(16) __nv_bfloat16  g_w2[(size_t)1536 * 384];

// ---------------- K0: ALL weight fp32 -> bf16 converts in ONE kernel ----------------
__global__ void k_wprep_all(const float* __restrict__ qkv_w, const float* __restrict__ proj_w,
                            const float* __restrict__ fc1_w, const float* __restrict__ fc2_w) {
    size_t i = ((size_t)blockIdx.x * 256 + threadIdx.x) * 4;
    const float* src; __nv_bfloat16* dst; size_t off;
    if (i < 442368)        { src = qkv_w;  dst = g_wq; off = i; }
    else if (i < 589824)   { src = proj_w; dst = g_wp; off = i - 442368; }
    else if (i < 1179648)  { src = fc1_w;  dst = g_w1; off = i - 589824; }
    else if (i < 1769472)  { src = fc2_w;  dst = g_w2; off = i - 1179648; }
    else return;
    float4 f = *(const float4*)&src[off];
    __nv_bfloat162 lo = __floats2bfloat162_rn(f.x, f.y);
    __nv_bfloat162 hi = __floats2bfloat162_rn(f.z, f.w);
    *(uint2*)&dst[off] = make_uint2(*(uint32_t*)&lo, *(uint32_t*)&hi);
}

// ---------------- K1: FUSED NCHW transpose + LN1 + window gather ----------------
// block = 32 tokens of one batch; writes g_xT [B,N,C] AND g_hln (windowed, bf16).
// smem tile [384][33] floats = 50688 B (dynamic).
#define TLN_SMEM (384 * 33 * 4)
__global__ void __launch_bounds__(256) k_tln(const float* __restrict__ x,
                                             const float* __restrict__ gam,
                                             const float* __restrict__ bet) {
    extern __shared__ float tl[];
    int b = blockIdx.y, n0 = blockIdx.x * 32;
    int tid = threadIdx.x;
    const float* xb = x + (size_t)b * CC_ * NS;
    for (int i = tid; i < 384 * 8; i += 256) {
        int c = i >> 3, v = i & 7;
        float4 f = *(const float4*)&xb[(size_t)c * NS + n0 + v * 4];
        float* d = &tl[c * 33 + v * 4];
        d[0] = f.x; d[1] = f.y; d[2] = f.z; d[3] = f.w;
    }
    __syncthreads();
    int t = tid >> 3, p = tid & 7;     // token t (0..31), part p: channels [p*48, p*48+48)
    int n = n0 + t;
    float s = 0.0f, sq = 0.0f;
#pragma unroll
    for (int j = 0; j < 48; j++) {
        float v = tl[(p * 48 + j) * 33 + t];
        s += v; sq += v * v;
    }
#pragma unroll
    for (int o = 4; o; o >>= 1) {
        s  += __shfl_xor_sync(0xffffffffu, s,  o);
        sq += __shfl_xor_sync(0xffffffffu, sq, o);
    }
    float mean = s * (1.0f / CC_);
    float var  = sq * (1.0f / CC_) - mean * mean;
    float rstd = rsqrtf(var + EPSV);

    int h = n / WW_, wpos = n % WW_;
    int gi = h % GG, si = h / GG;
    int gj = wpos % GG, sj = wpos / GG;
    size_t orow = ((size_t)((b * GG + gi) * GG + gj)) * 64 + si * SSZ + sj;
    float*         xt = g_xT  + ((size_t)b * NS + n) * CC_;
    __nv_bfloat16* hl = g_hln + orow * CC_;
#pragma unroll
    for (int j4 = 0; j4 < 48; j4 += 4) {
        int c = p * 48 + j4;
        float v0 = tl[(c + 0) * 33 + t], v1 = tl[(c + 1) * 33 + t];
        float v2 = tl[(c + 2) * 33 + t], v3 = tl[(c + 3) * 33 + t];
        *(float4*)&xt[c] = make_float4(v0, v1, v2, v3);
        __nv_bfloat162 h0 = __floats2bfloat162_rn((v0 - mean) * rstd * gam[c + 0] + bet[c + 0],
                                                  (v1 - mean) * rstd * gam[c + 1] + bet[c + 1]);
        __nv_bfloat162 h1 = __floats2bfloat162_rn((v2 - mean) * rstd * gam[c + 2] + bet[c + 2],
                                                  (v3 - mean) * rstd * gam[c + 3] + bet[c + 3]);
        *(uint2*)&hl[c] = make_uint2(*(uint32_t*)&h0, *(uint32_t*)&h1);
    }
}

// ---------------- K6: LayerNorm 2 (token-major) ----------------
__global__ void k_layernorm2(const float* __restrict__ gam, const float* __restrict__ bet) {
    int r   = blockIdx.x;
    int tid = threadIdx.x;          // 128
    const float* src = g_x1 + (size_t)r * CC_;
    float v0 = src[tid], v1 = src[tid + 128], v2 = src[tid + 256];
    float s  = v0 + v1 + v2;
    float sq = v0 * v0 + v1 * v1 + v2 * v2;
#pragma unroll
    for (int o = 16; o; o >>= 1) {
        s  += __shfl_xor_sync(0xffffffffu, s,  o);
        sq += __shfl_xor_sync(0xffffffffu, sq, o);
    }
    __shared__ float ws[4], wq[4];
    int w = tid >> 5, l = tid & 31;
    if (l == 0) { ws[w] = s; wq[w] = sq; }
    __syncthreads();
    float mean = (ws[0] + ws[1] + ws[2] + ws[3]) * (1.0f / CC_);
    float var  = (wq[0] + wq[1] + wq[2] + wq[3]) * (1.0f / CC_) - mean * mean;
    float rstd = rsqrtf(var + EPSV);
    __nv_bfloat16* dst = g_ln2 + (size_t)r * CC_;
    dst[tid]       = __float2bfloat16((v0 - mean) * rstd * gam[tid]       + bet[tid]);
    dst[tid + 128] = __float2bfloat16((v1 - mean) * rstd * gam[tid + 128] + bet[tid + 128]);
    dst[tid + 256] = __float2bfloat16((v2 - mean) * rstd * gam[tid + 256] + bet[tid + 256]);
}

// ---------------- wmma GEMM, 128x128 CTA tile, 32x64 warp tile, K-tile 64, 2-stage ----------------
// 8 warps in 4(M) x 2(N). 2 CTAs/SM (launch_bounds caps regs at 128).
// Per iter: 1 wait_group + 2 syncthreads, 32 MMAs/warp between barriers.
// stage: A 128 x 72 elems (18432 B) + B 64 x 136 elems (17408 B) = 35840 B; x2 = 71680 B.
// MODE 0: QKV   A=g_hln  K=384  N=1152 -> g_qkv (bf16)
// MODE 1: PROJ  A=g_o    K=384  N=384  -> g_x1 = xT + gamma1*(A@W + b)  (window->token scatter)
// MODE 2: FC1   A=g_ln2  K=384  N=1536 -> g_m1 = bf16(A@W + b)
// MODE 3: FC2   A=g_mg   K=1536 N=384  -> out[b,c,n] = x1 + gamma2*(A@W + b)  (NCHW permute)
#define STG_BYTES 35840
#define GEMM_DSMEM (2 * STG_BYTES)

__device__ __forceinline__ uint32_t sptr(const void* p) {
    uint32_t a;
    asm("{ .reg .u64 t; cvta.to.shared.u64 t, %1; cvt.u32.u64 %0, t; }" : "=r"(a) : "l"(p));
    return a;
}

template<int MODE>
__global__ void __launch_bounds__(256, 2) k_gemm(
    const float* __restrict__ bias, const float* __restrict__ gamma,
    float* __restrict__ outp)
{
    constexpr int Kdim  = (MODE == 3) ? 1536 : 384;
    constexpr int Ncols = (MODE == 0) ? 1152 : ((MODE == 2) ? 1536 : 384);
    constexpr int NKT   = Kdim / 64;

    const __nv_bfloat16* A  = (MODE == 0) ? g_hln : (MODE == 1) ? g_o : (MODE == 2) ? g_ln2 : g_mg;
    const __nv_bfloat16* Bw = (MODE == 0) ? g_wq  : (MODE == 1) ? g_wp : (MODE == 2) ? g_w1 : g_w2;

    extern __shared__ __align__(16) char dsm[];

    int n0 = blockIdx.x * 128;
    int m0 = blockIdx.y * 128;
    int tid  = threadIdx.x;
    int warp = tid >> 5, lane = tid & 31;
    int wm = warp & 3, wn = warp >> 2;   // warp tile: rows [wm*32,+32), cols [wn*64,+64)

    wmma::fragment<wmma::accumulator, 16, 16, 16, float> acc[2][4];
#pragma unroll
    for (int i = 0; i < 2; i++)
#pragma unroll
        for (int j = 0; j < 4; j++) wmma::fill_fragment(acc[i][j], 0.0f);

    // stage: A at st (128 rows x 72 elems), B at st+18432 (64 rows x 136 elems)
    auto load_stage = [&](int kt, int buf) {
        int k0 = kt * 64;
        char* st = dsm + buf * STG_BYTES;
#pragma unroll
        for (int s = 0; s < 8; s++) {
            int i = tid + s * 256;
            uint32_t dst; const __nv_bfloat16* src;
            if (i < 1024) {          // A: 128 rows x 8 chunks of 16B
                int r = i >> 3, c = i & 7;
                dst = sptr(st + (r * 72 + c * 8) * 2);
                src = A + (size_t)(m0 + r) * Kdim + k0 + c * 8;
            } else {                 // B: 64 rows x 16 chunks of 16B
                int j = i - 1024, r = j >> 4, c = j & 15;
                dst = sptr(st + 18432 + (r * 136 + c * 8) * 2);
                src = Bw + (size_t)(k0 + r) * Ncols + n0 + c * 8;
            }
            asm volatile("cp.async.cg.shared.global [%0], [%1], 16;" :: "r"(dst), "l"(src));
        }
        asm volatile("cp.async.commit_group;" ::: "memory");
    };

    load_stage(0, 0);

    for (int kt = 0; kt < NKT; ++kt) {
        int buf = kt & 1;
        if (kt + 1 < NKT) load_stage(kt + 1, buf ^ 1);
        else asm volatile("cp.async.commit_group;" ::: "memory");   // uniform group count
        asm volatile("cp.async.wait_group 1;" ::: "memory");        // group kt complete
        __syncthreads();                                            // stage kt visible

        const __nv_bfloat16* cA = (const __nv_bfloat16*)(dsm + buf * STG_BYTES);
        const __nv_bfloat16* cB = (const __nv_bfloat16*)(dsm + buf * STG_BYTES + 18432);
#pragma unroll
        for (int ks = 0; ks < 64; ks += 16) {
            wmma::fragment<wmma::matrix_a, 16, 16, 16, __nv_bfloat16, wmma::row_major> af[2];
            wmma::fragment<wmma::matrix_b, 16, 16, 16, __nv_bfloat16, wmma::row_major> bf[4];
#pragma unroll
            for (int i = 0; i < 2; i++)
                wmma::load_matrix_sync(af[i], &cA[(wm * 32 + i * 16) * 72 + ks], 72);
#pragma unroll
            for (int j = 0; j < 4; j++)
                wmma::load_matrix_sync(bf[j], &cB[ks * 136 + wn * 64 + j * 16], 136);
#pragma unroll
            for (int i = 0; i < 2; i++)
#pragma unroll
                for (int j = 0; j < 4; j++)
                    wmma::mma_sync(acc[i][j], af[i], bf[j], acc[i][j]);
        }
        __syncthreads();    // all warps done reading buf before next iter loads into it
    }

    float* sEpi = (float*)dsm + warp * 320;   // 8 warps x 16x20 floats = 10240 B (fits stage 0 A)

#pragma unroll
    for (int i = 0; i < 2; i++) {
#pragma unroll
        for (int j = 0; j < 4; j++) {
            wmma::store_matrix_sync(sEpi, acc[i][j], 20, wmma::mem_row_major);
            __syncwarp();
            int growb = m0 + wm * 32 + i * 16;
            int gcolb = n0 + wn * 64 + j * 16;
#pragma unroll
            for (int e = 0; e < 8; e++) {
                int idx = e * 32 + lane;
                int rr, cc;
                if (MODE == 3) { cc = idx >> 4; rr = idx & 15; }     // column-major: coalesced over n
                else           { rr = idx >> 4; cc = idx & 15; }
                float v = sEpi[rr * 20 + cc];
                int grow = growb + rr, gcol = gcolb + cc;
                if (MODE == 0) {
                    g_qkv[(size_t)grow * Ncols + gcol] = __float2bfloat16(v);
                } else if (MODE == 2) {
                    g_m1[(size_t)grow * Ncols + gcol] = __float2bfloat16(v + bias[gcol]);
                } else if (MODE == 1) {
                    int win = grow >> 6, t = grow & 63;
                    int b = win / 49, wi = win % 49;
                    int gi = wi / 7, gj = wi % 7;
                    int si = t >> 3, sj = t & 7;
                    int h = si * GG + gi, wp = sj * GG + gj;
                    size_t ridx = ((size_t)b * NS + h * WW_ + wp) * CC_ + gcol;
                    g_x1[ridx] = g_xT[ridx] + gamma[gcol] * (v + bias[gcol]);
                } else {  // MODE 3
                    int b = grow / NS, n = grow % NS;
                    float ov = g_x1[(size_t)grow * CC_ + gcol]
                             + gamma[gcol] * (v + bias[gcol]);
                    outp[((size_t)b * CC_ + gcol) * NS + n] = ov;
                }
            }
            __syncwarp();
        }
    }
}

// ---------------- K4: attention, one block per (window, head), 4 warps ----------------
__global__ void __launch_bounds__(128) k_attn() {
    int win  = blockIdx.x;
    int head = blockIdx.y;
    __shared__ __nv_bfloat16 sq[64 * 56], sk[64 * 56], sv[64 * 56];
    __shared__ float sS[64 * 68];
    __shared__ __nv_bfloat16 sP[64 * 72];
    __shared__ float red[128];
    int tid = threadIdx.x;

    size_t base = (size_t)win * 64 * 1152;
#pragma unroll
    for (int m = 0; m < 3; m++) {
        const __nv_bfloat16* src = g_qkv + base + m * 384 + head * 48;
        __nv_bfloat16* dst = (m == 0) ? sq : (m == 1) ? sk : sv;
        for (int li = tid; li < 64 * 6; li += 128) {
            int t = li / 6, dg = (li % 6) * 8;
            *(uint4*)&dst[t * 56 + dg] = *(const uint4*)&src[(size_t)t * 1152 + dg];
        }
    }
    __syncthreads();

    int warp = tid >> 5;
    int m0 = warp * 16;
    {   // S = q @ k^T   [64x64], K=48
        wmma::fragment<wmma::accumulator, 16, 16, 16, float> acc[4];
#pragma unroll
        for (int j = 0; j < 4; j++) wmma::fill_fragment(acc[j], 0.0f);
#pragma unroll
        for (int k = 0; k < 48; k += 16) {
            wmma::fragment<wmma::matrix_a, 16, 16, 16, __nv_bfloat16, wmma::row_major> af;
            wmma::load_matrix_sync(af, &sq[m0 * 56 + k], 56);
#pragma unroll
            for (int j = 0; j < 4; j++) {
                wmma::fragment<wmma::matrix_b, 16, 16, 16, __nv_bfloat16, wmma::col_major> bf;
                wmma::load_matrix_sync(bf, &sk[(j * 16) * 56 + k], 56);
                wmma::mma_sync(acc[j], af, bf, acc[j]);
            }
        }
#pragma unroll
        for (int j = 0; j < 4; j++)
            wmma::store_matrix_sync(&sS[m0 * 68 + j * 16], acc[j], 68, wmma::mem_row_major);
    }
    __syncthreads();

    {   // softmax: 128 threads, 2 per row, smem combine
        const float scale = 0.14433756729740643f;  // 48^-0.5
        int row = tid & 63, half = tid >> 6;
        const float* Srow = &sS[row * 68 + half * 32];
        float buf[32];
        float mx = -1e30f;
#pragma unroll
        for (int j = 0; j < 32; j++) { buf[j] = Srow[j] * scale; mx = fmaxf(mx, buf[j]); }
        red[tid] = mx;
        __syncthreads();
        mx = fmaxf(red[row], red[row + 64]);
        float sum = 0.0f;
#pragma unroll
        for (int j = 0; j < 32; j++) { buf[j] = __expf(buf[j] - mx); sum += buf[j]; }
        __syncthreads();
        red[tid] = sum;
        __syncthreads();
        float inv = 1.0f / (red[row] + red[row + 64]);
        __nv_bfloat16* Prow = &sP[row * 72 + half * 32];
#pragma unroll
        for (int j = 0; j < 32; j++) Prow[j] = __float2bfloat16(buf[j] * inv);
    }
    __syncthreads();

    {   // O = P @ V   [64x48], K=64
        wmma::fragment<wmma::accumulator, 16, 16, 16, float> acc[3];
#pragma unroll
        for (int j = 0; j < 3; j++) wmma::fill_fragment(acc[j], 0.0f);
#pragma unroll
        for (int k = 0; k < 64; k += 16) {
            wmma::fragment<wmma::matrix_a, 16, 16, 16, __nv_bfloat16, wmma::row_major> af;
            wmma::load_matrix_sync(af, &sP[m0 * 72 + k], 72);
#pragma unroll
            for (int j = 0; j < 3; j++) {
                wmma::fragment<wmma::matrix_b, 16, 16, 16, __nv_bfloat16, wmma::row_major> bf;
                wmma::load_matrix_sync(bf, &sv[k * 56 + j * 16], 56);
                wmma::mma_sync(acc[j], af, bf, acc[j]);
            }
        }
#pragma unroll
        for (int j = 0; j < 3; j++)
            wmma::store_matrix_sync(&sS[m0 * 68 + j * 16], acc[j], 68, wmma::mem_row_major);
    }
    __syncthreads();

    __nv_bfloat16* dst = g_o + (size_t)win * 64 * 384 + head * 48;
    for (int li = tid; li < 64 * 48; li += 128) {
        int t = li / 48, d = li % 48;
        dst[(size_t)t * 384 + d] = __float2bfloat16(sS[t * 68 + d]);
    }
}

// ---------------- K8: depthwise 3x3 conv + bias + exact GELU (4 rows/block) ----------------
__global__ void __launch_bounds__(256) k_dwconv(const float* __restrict__ wgt,
                                                const float* __restrict__ bias) {
    __shared__ __nv_bfloat16 s[6 * 58 * 64];
    int b = blockIdx.y, h0 = blockIdx.x * 4;   // grid (14, 32)
    int tid = threadIdx.x;
    int c = tid & 63, sub = tid >> 6;

    for (int cc = 0; cc < HID; cc += 64) {
        __syncthreads();
        for (int li = tid; li < 6 * 58 * 8; li += 256) {
            int hr = li / 464;
            int rem = li % 464;
            int wi = rem >> 3;
            int grp = (rem & 7) * 8;
            int hh = h0 - 1 + hr, ww = wi - 1;
            uint4 val = make_uint4(0u, 0u, 0u, 0u);
            if (hh >= 0 && hh < HH_ && ww >= 0 && ww < WW_)
                val = *(const uint4*)&g_m1[((size_t)b * NS + hh * WW_ + ww) * HID + cc + grp];
            *(uint4*)&s[(hr * 58 + wi) * 64 + grp] = val;
        }
        __syncthreads();

        int ch = cc + c;
        float w9[9];
#pragma unroll
        for (int i = 0; i < 9; i++) w9[i] = wgt[ch * 9 + i];
        float bv = bias[ch];
        int h = h0 + sub;
        for (int w0 = 0; w0 < WW_; w0++) {
            float acc = bv;
#pragma unroll
            for (int dy = 0; dy < 3; dy++)
#pragma unroll
                for (int dx = 0; dx < 3; dx++)
                    acc += __bfloat162float(s[((sub + dy) * 58 + w0 + dx) * 64 + c]) * w9[dy * 3 + dx];
            float gl = 0.5f * acc * (1.0f + erff(acc * 0.70710678118f));
            g_mg[((size_t)b * NS + h * WW_ + w0) * HID + ch] = __float2bfloat16(gl);
        }
    }
}

// ---------------- launch ----------------
extern "C" void kernel_launch(void* const* d_in, const int* in_sizes, int n_in,
                              void* d_out, int out_size) {
    (void)in_sizes; (void)n_in; (void)out_size;
    const float* x      = (const float*)d_in[0];
    const float* ln1_g  = (const float*)d_in[1];
    const float* ln1_b  = (const float*)d_in[2];
    const float* qkv_w  = (const float*)d_in[3];
    const float* proj_w = (const float*)d_in[4];
    const float* proj_b = (const float*)d_in[5];
    const float* ln2_g  = (const float*)d_in[6];
    const float* ln2_b  = (const float*)d_in[7];
    const float* fc1_w  = (const float*)d_in[8];
    const float* fc1_b  = (const float*)d_in[9];
    const float* dw_w   = (const float*)d_in[10];
    const float* dw_b   = (const float*)d_in[11];
    const float* fc2_w  = (const float*)d_in[12];
    const float* fc2_b  = (const float*)d_in[13];
    const float* gamma1 = (const float*)d_in[14];
    const float* gamma2 = (const float*)d_in[15];
    float* out = (float*)d_out;

    // idempotent, deterministic, capture-safe
    cudaFuncSetAttribute(k_tln,     cudaFuncAttributeMaxDynamicSharedMemorySize, TLN_SMEM);
    cudaFuncSetAttribute(k_gemm<0>, cudaFuncAttributeMaxDynamicSharedMemorySize, GEMM_DSMEM);
    cudaFuncSetAttribute(k_gemm<1>, cudaFuncAttributeMaxDynamicSharedMemorySize, GEMM_DSMEM);
    cudaFuncSetAttribute(k_gemm<2>, cudaFuncAttributeMaxDynamicSharedMemorySize, GEMM_DSMEM);
    cudaFuncSetAttribute(k_gemm<3>, cudaFuncAttributeMaxDynamicSharedMemorySize, GEMM_DSMEM);

    k_wprep_all<<<1728, 256>>>(qkv_w, proj_w, fc1_w, fc2_w);                        // 0
    k_tln<<<dim3(NS / 32, BB), 256, TLN_SMEM>>>(x, ln1_g, ln1_b);                   // 1
    k_gemm<0><<<dim3(1152 / 128, MR / 128), 256, GEMM_DSMEM>>>(nullptr, nullptr, nullptr); // 2
    k_attn<<<dim3(NWIN, NHEADS), 128>>>();                                          // 3
    k_gemm<1><<<dim3(384 / 128, MR / 128), 256, GEMM_DSMEM>>>(proj_b, gamma1, nullptr);    // 4
    k_layernorm2<<<MR, 128>>>(ln2_g, ln2_b);                                        // 5
    k_gemm<2><<<dim3(1536 / 128, MR / 128), 256, GEMM_DSMEM>>>(fc1_b, nullptr, nullptr);   // 6
    k_dwconv<<<dim3(14, BB), 256>>>(dw_w, dw_b);                                    // 7
    k_gemm<3><<<dim3(384 / 128, MR / 128), 256, GEMM_DSMEM>>>(fc2_b, gamma2, out);  // 8
}

// round 13
// speedup vs baseline: 1.2742x; 1.1319x over previous
#include <cuda_runtime.h>
#include <cuda_bf16.h>
#include <cuda_fp8.h>
#include <mma.h>
#include <cstdint>

using namespace nvcuda;

// ---------------- problem constants ----------------
#define BB   32
#define CC_  384
#define HH_  56
#define WW_  56
#define NS   3136        // H*W
#define MR   100352      // B*N
#define HID  1536
#define NHEADS 8
#define HD   48
#define GG   7           // grid size
#define SSZ  8           // sparse size
#define NWIN 1568        // B*GG*GG
#define EPSV 1e-5f

// ---------------- scratch (device globals; allocation-free) ----------------
__device__ __align__(16) float          g_xT [(size_t)MR * CC_];       // [B,N,C] fp32
__device__ __align__(16) uint8_t        g_hln[(size_t)MR * CC_];       // LN1 out e4m3, window-major
__device__ __align__(16) __nv_bfloat16  g_qkv[(size_t)MR * 3 * CC_];   // window-major (bf16)
__device__ __align__(16) uint8_t        g_o  [(size_t)MR * CC_];       // attn out e4m3, window-major
__device__ __align__(16) float          g_x1 [(size_t)MR * CC_];       // residual1, token-major
__device__ __align__(16) uint8_t        g_ln2[(size_t)MR * CC_];       // LN2 out e4m3
__device__ __align__(16) __nv_bfloat16  g_m1 [(size_t)MR * HID];       // fc1 out (bf16, dwconv reads)
__device__ __align__(16) uint8_t        g_mg [(size_t)MR * HID];       // dwconv+gelu out e4m3
// fp8 weights, TRANSPOSED: [N, K] (K contiguous)
__device__ __align__(16) uint8_t        g_wq[(size_t)1152 * 384];
__device__ __align__(16) uint8_t        g_wp[(size_t)384 * 384];
__device__ __align__(16) uint8_t        g_w1[(size_t)1536 * 384];
__device__ __align__(16) uint8_t        g_w2[(size_t)384 * 1536];

// ---------------- fp8 helpers (consistent byte order everywhere) ----------------
__device__ __forceinline__ uint8_t q1(float v) {
    return (uint8_t)__nv_cvt_float_to_fp8(v, __NV_SATFINITE, __NV_E4M3);
}
__device__ __forceinline__ uint32_t q4(float v0, float v1, float v2, float v3) {
    return (uint32_t)q1(v0) | ((uint32_t)q1(v1) << 8) |
           ((uint32_t)q1(v2) << 16) | ((uint32_t)q1(v3) << 24);
}

__device__ __forceinline__ uint32_t sptr(const void* p) {
    uint32_t a;
    asm("{ .reg .u64 t; cvta.to.shared.u64 t, %1; cvt.u32.u64 %0, t; }" : "=r"(a) : "l"(p));
    return a;
}
__device__ __forceinline__ void ldsm4(uint32_t* r, uint32_t addr) {
    asm volatile("ldmatrix.sync.aligned.m8n8.x4.shared.b16 {%0,%1,%2,%3}, [%4];"
        : "=r"(r[0]), "=r"(r[1]), "=r"(r[2]), "=r"(r[3]) : "r"(addr));
}
__device__ __forceinline__ void mma_fp8(float* c, const uint32_t* a, const uint32_t* b) {
    asm volatile(
        "mma.sync.aligned.m16n8k32.row.col.f32.e4m3.e4m3.f32 "
        "{%0,%1,%2,%3}, {%4,%5,%6,%7}, {%8,%9}, {%0,%1,%2,%3};"
        : "+f"(c[0]), "+f"(c[1]), "+f"(c[2]), "+f"(c[3])
        : "r"(a[0]), "r"(a[1]), "r"(a[2]), "r"(a[3]), "r"(b[0]), "r"(b[1]));
}

// ---------------- K0: weight transpose + fp8 quantize: Wt[n][k] = W[k][n] ----------------
template<int WID>
__global__ void k_wprepT(const float* __restrict__ W) {
    constexpr int K = (WID == 3) ? 1536 : 384;   // output inner dim
    constexpr int N = (WID == 0) ? 1152 : (WID == 2) ? 1536 : 384;
    uint8_t* Wt = (WID == 0) ? g_wq : (WID == 1) ? g_wp : (WID == 2) ? g_w1 : g_w2;
    __shared__ float t[32][33];
    int k0 = blockIdx.x * 32, nb = blockIdx.y * 32;
    int tx = threadIdx.x, ty = threadIdx.y;   // (32,8)
#pragma unroll
    for (int i = 0; i < 32; i += 8)
        t[ty + i][tx] = W[(size_t)(k0 + ty + i) * N + nb + tx];
    __syncthreads();
#pragma unroll
    for (int i = 0; i < 32; i += 8)
        Wt[(size_t)(nb + ty + i) * K + k0 + tx] = q1(t[tx][ty + i]);
}

// ---------------- K1: FUSED NCHW transpose + LN1 + window gather (fp8 out) ----------------
#define TLN_SMEM (384 * 33 * 4)
__global__ void __launch_bounds__(256) k_tln(const float* __restrict__ x,
                                             const float* __restrict__ gam,
                                             const float* __restrict__ bet) {
    extern __shared__ float tl[];
    int b = blockIdx.y, n0 = blockIdx.x * 32;
    int tid = threadIdx.x;
    const float* xb = x + (size_t)b * CC_ * NS;
    for (int i = tid; i < 384 * 8; i += 256) {
        int c = i >> 3, v = i & 7;
        float4 f = *(const float4*)&xb[(size_t)c * NS + n0 + v * 4];
        float* d = &tl[c * 33 + v * 4];
        d[0] = f.x; d[1] = f.y; d[2] = f.z; d[3] = f.w;
    }
    __syncthreads();
    int t = tid >> 3, p = tid & 7;     // token t (0..31), part p: channels [p*48, +48)
    int n = n0 + t;
    float s = 0.0f, sq = 0.0f;
#pragma unroll
    for (int j = 0; j < 48; j++) {
        float v = tl[(p * 48 + j) * 33 + t];
        s += v; sq += v * v;
    }
#pragma unroll
    for (int o = 4; o; o >>= 1) {
        s  += __shfl_xor_sync(0xffffffffu, s,  o);
        sq += __shfl_xor_sync(0xffffffffu, sq, o);
    }
    float mean = s * (1.0f / CC_);
    float var  = sq * (1.0f / CC_) - mean * mean;
    float rstd = rsqrtf(var + EPSV);

    int h = n / WW_, wpos = n % WW_;
    int gi = h % GG, si = h / GG;
    int gj = wpos % GG, sj = wpos / GG;
    size_t orow = ((size_t)((b * GG + gi) * GG + gj)) * 64 + si * SSZ + sj;
    float*   xt = g_xT  + ((size_t)b * NS + n) * CC_;
    uint8_t* hl = g_hln + orow * CC_;
#pragma unroll
    for (int j4 = 0; j4 < 48; j4 += 4) {
        int c = p * 48 + j4;
        float v0 = tl[(c + 0) * 33 + t], v1 = tl[(c + 1) * 33 + t];
        float v2 = tl[(c + 2) * 33 + t], v3 = tl[(c + 3) * 33 + t];
        *(float4*)&xt[c] = make_float4(v0, v1, v2, v3);
        *(uint32_t*)&hl[c] = q4((v0 - mean) * rstd * gam[c + 0] + bet[c + 0],
                                (v1 - mean) * rstd * gam[c + 1] + bet[c + 1],
                                (v2 - mean) * rstd * gam[c + 2] + bet[c + 2],
                                (v3 - mean) * rstd * gam[c + 3] + bet[c + 3]);
    }
}

// ---------------- K6: LayerNorm 2 (token-major, fp8 out) ----------------
__global__ void k_layernorm2(const float* __restrict__ gam, const float* __restrict__ bet) {
    int r   = blockIdx.x;
    int tid = threadIdx.x;          // 128
    const float* src = g_x1 + (size_t)r * CC_;
    float v0 = src[tid], v1 = src[tid + 128], v2 = src[tid + 256];
    float s  = v0 + v1 + v2;
    float sq = v0 * v0 + v1 * v1 + v2 * v2;
#pragma unroll
    for (int o = 16; o; o >>= 1) {
        s  += __shfl_xor_sync(0xffffffffu, s,  o);
        sq += __shfl_xor_sync(0xffffffffu, sq, o);
    }
    __shared__ float ws[4], wq[4];
    int w = tid >> 5, l = tid & 31;
    if (l == 0) { ws[w] = s; wq[w] = sq; }
    __syncthreads();
    float mean = (ws[0] + ws[1] + ws[2] + ws[3]) * (1.0f / CC_);
    float var  = (wq[0] + wq[1] + wq[2] + wq[3]) * (1.0f / CC_) - mean * mean;
    float rstd = rsqrtf(var + EPSV);
    uint8_t* dst = g_ln2 + (size_t)r * CC_;
    dst[tid]       = q1((v0 - mean) * rstd * gam[tid]       + bet[tid]);
    dst[tid + 128] = q1((v1 - mean) * rstd * gam[tid + 128] + bet[tid + 128]);
    dst[tid + 256] = q1((v2 - mean) * rstd * gam[tid + 256] + bet[tid + 256]);
}

// ---------------- FP8 GEMM: 128x128 CTA, 32x64 warp tile, K-tile 64B, 2-stage ----------------
// 8 warps 4(M) x 2(N). mma.m16n8k32 e4m3; A [M,K] fp8, B [N,K] fp8 (both K-contig).
// smem rows padded to 80B: conflict-free ldmatrix (20-word row stride).
// stage = A 128x80 + B 128x80 = 20480 B; 2 stages = 40960 B; 2 CTAs/SM.
// MODE 0: QKV   A=g_hln  K=384  N=1152 -> g_qkv (bf16)
// MODE 1: PROJ  A=g_o    K=384  N=384  -> g_x1 = xT + gamma1*(A@W + b)  (window->token scatter)
// MODE 2: FC1   A=g_ln2  K=384  N=1536 -> g_m1 = bf16(A@W + b)
// MODE 3: FC2   A=g_mg   K=1536 N=384  -> out[b,c,n] = x1 + gamma2*(A@W + b)  (NCHW permute)
#define STG_BYTES 20480
#define GEMM_DSMEM (2 * STG_BYTES)

template<int MODE>
__global__ void __launch_bounds__(256, 2) k_gemm(
    const float* __restrict__ bias, const float* __restrict__ gamma,
    float* __restrict__ outp)
{
    constexpr int Kdim  = (MODE == 3) ? 1536 : 384;
    constexpr int Ncols = (MODE == 0) ? 1152 : ((MODE == 2) ? 1536 : 384);
    constexpr int NKT   = Kdim / 64;

    const uint8_t* A  = (MODE == 0) ? g_hln : (MODE == 1) ? g_o : (MODE == 2) ? g_ln2 : g_mg;
    const uint8_t* Bw = (MODE == 0) ? g_wq  : (MODE == 1) ? g_wp : (MODE == 2) ? g_w1 : g_w2;

    extern __shared__ __align__(16) char dsm[];
    uint32_t dbase = sptr(dsm);

    int n0 = blockIdx.x * 128;
    int m0 = blockIdx.y * 128;
    int tid  = threadIdx.x;
    int warp = tid >> 5, lane = tid & 31;
    int wm = warp & 3, wn = warp >> 2;   // warp tile rows [wm*32,+32), cols [wn*64,+64)

    float acc[2][8][4];
#pragma unroll
    for (int i = 0; i < 2; i++)
#pragma unroll
        for (int j = 0; j < 8; j++)
#pragma unroll
            for (int q = 0; q < 4; q++) acc[i][j][q] = 0.0f;

    // stage: A at st (128 rows x 80B), B at st+10240 (128 n-rows x 80B); 64B data/row
    auto load_stage = [&](int kt, int buf) {
        int k0 = kt * 64;
        uint32_t st = dbase + buf * STG_BYTES;
#pragma unroll
        for (int s = 0; s < 4; s++) {
            int i = tid + s * 256;
            uint32_t dst; const uint8_t* src;
            if (i < 512) {           // A: 128 rows x 4 chunks of 16B
                int r = i >> 2, c = i & 3;
                dst = st + r * 80 + c * 16;
                src = A + (size_t)(m0 + r) * Kdim + k0 + c * 16;
            } else {                 // B: 128 n-rows x 4 chunks of 16B
                int j = i - 512, r = j >> 2, c = j & 3;
                dst = st + 10240 + r * 80 + c * 16;
                src = Bw + (size_t)(n0 + r) * Kdim + k0 + c * 16;
            }
            asm volatile("cp.async.cg.shared.global [%0], [%1], 16;" :: "r"(dst), "l"(src));
        }
        asm volatile("cp.async.commit_group;" ::: "memory");
    };

    load_stage(0, 0);

    int lrow = lane & 15, lhi = lane >> 4;
    for (int kt = 0; kt < NKT; ++kt) {
        int buf = kt & 1;
        if (kt + 1 < NKT) load_stage(kt + 1, buf ^ 1);
        else asm volatile("cp.async.commit_group;" ::: "memory");
        asm volatile("cp.async.wait_group 1;" ::: "memory");
        __syncthreads();

        uint32_t stA = dbase + buf * STG_BYTES;
        uint32_t stB = stA + 10240;
#pragma unroll
        for (int h = 0; h < 2; h++) {           // two k=32 steps per 64B tile
            uint32_t a[2][4], b[8][2];
#pragma unroll
            for (int i = 0; i < 2; i++)
                ldsm4(a[i], stA + (wm * 32 + i * 16 + lrow) * 80 + (h * 2 + lhi) * 16);
#pragma unroll
            for (int jp = 0; jp < 4; jp++) {
                uint32_t t4[4];
                ldsm4(t4, stB + (wn * 64 + jp * 16 + lrow) * 80 + (h * 2 + lhi) * 16);
                b[2 * jp][0] = t4[0];  b[2 * jp][1] = t4[2];
                b[2 * jp + 1][0] = t4[1]; b[2 * jp + 1][1] = t4[3];
            }
#pragma unroll
            for (int i = 0; i < 2; i++)
#pragma unroll
                for (int j = 0; j < 8; j++)
                    mma_fp8(acc[i][j], a[i], b[j]);
        }
        __syncthreads();
    }

    // ---------------- epilogue: 2 passes; warp stages 16x64 fp32 (16x68 padded) ----------------
    float* sEpi = (float*)dsm + warp * 1088;     // 16*68 floats = 4352 B/warp; 8 warps = 34816 B
    int row0 = lane >> 2, col0 = 2 * (lane & 3);

#pragma unroll
    for (int i = 0; i < 2; i++) {
#pragma unroll
        for (int j = 0; j < 8; j++) {
            sEpi[row0 * 68 + 8 * j + col0]           = acc[i][j][0];
            sEpi[row0 * 68 + 8 * j + col0 + 1]       = acc[i][j][1];
            sEpi[(row0 + 8) * 68 + 8 * j + col0]     = acc[i][j][2];
            sEpi[(row0 + 8) * 68 + 8 * j + col0 + 1] = acc[i][j][3];
        }
        __syncwarp();
        int growb = m0 + wm * 32 + i * 16;
        int gcolb = n0 + wn * 64;
#pragma unroll
        for (int e = 0; e < 32; e++) {
            int idx = e * 32 + lane;
            int rr, cc;
            if (MODE == 3) { cc = idx >> 4; rr = idx & 15; }     // column-major: coalesced over n
            else           { rr = idx >> 6; cc = idx & 63; }
            float v = sEpi[rr * 68 + cc];
            int grow = growb + rr, gcol = gcolb + cc;
            if (MODE == 0) {
                g_qkv[(size_t)grow * Ncols + gcol] = __float2bfloat16(v);
            } else if (MODE == 2) {
                g_m1[(size_t)grow * Ncols + gcol] = __float2bfloat16(v + bias[gcol]);
            } else if (MODE == 1) {
                int win = grow >> 6, t = grow & 63;
                int b = win / 49, wi = win % 49;
                int gi = wi / 7, gj = wi % 7;
                int si = t >> 3, sj = t & 7;
                int h = si * GG + gi, wp = sj * GG + gj;
                size_t ridx = ((size_t)b * NS + h * WW_ + wp) * CC_ + gcol;
                g_x1[ridx] = g_xT[ridx] + gamma[gcol] * (v + bias[gcol]);
            } else {  // MODE 3
                int b = grow / NS, n = grow % NS;
                float ov = g_x1[(size_t)grow * CC_ + gcol]
                         + gamma[gcol] * (v + bias[gcol]);
                outp[((size_t)b * CC_ + gcol) * NS + n] = ov;
            }
        }
        __syncwarp();
    }
}

// ---------------- K4: attention, one block per (window, head), 4 warps ----------------
__global__ void __launch_bounds__(128) k_attn() {
    int win  = blockIdx.x;
    int head = blockIdx.y;
    __shared__ __nv_bfloat16 sq[64 * 56], sk[64 * 56], sv[64 * 56];
    __shared__ float sS[64 * 68];
    __shared__ __nv_bfloat16 sP[64 * 72];
    __shared__ float red[128];
    int tid = threadIdx.x;

    size_t base = (size_t)win * 64 * 1152;
#pragma unroll
    for (int m = 0; m < 3; m++) {
        const __nv_bfloat16* src = g_qkv + base + m * 384 + head * 48;
        __nv_bfloat16* dst = (m == 0) ? sq : (m == 1) ? sk : sv;
        for (int li = tid; li < 64 * 6; li += 128) {
            int t = li / 6, dg = (li % 6) * 8;
            *(uint4*)&dst[t * 56 + dg] = *(const uint4*)&src[(size_t)t * 1152 + dg];
        }
    }
    __syncthreads();

    int warp = tid >> 5;
    int m0 = warp * 16;
    {   // S = q @ k^T   [64x64], K=48
        wmma::fragment<wmma::accumulator, 16, 16, 16, float> acc[4];
#pragma unroll
        for (int j = 0; j < 4; j++) wmma::fill_fragment(acc[j], 0.0f);
#pragma unroll
        for (int k = 0; k < 48; k += 16) {
            wmma::fragment<wmma::matrix_a, 16, 16, 16, __nv_bfloat16, wmma::row_major> af;
            wmma::load_matrix_sync(af, &sq[m0 * 56 + k], 56);
#pragma unroll
            for (int j = 0; j < 4; j++) {
                wmma::fragment<wmma::matrix_b, 16, 16, 16, __nv_bfloat16, wmma::col_major> bf;
                wmma::load_matrix_sync(bf, &sk[(j * 16) * 56 + k], 56);
                wmma::mma_sync(acc[j], af, bf, acc[j]);
            }
        }
#pragma unroll
        for (int j = 0; j < 4; j++)
            wmma::store_matrix_sync(&sS[m0 * 68 + j * 16], acc[j], 68, wmma::mem_row_major);
    }
    __syncthreads();

    {   // softmax: 128 threads, 2 per row, smem combine
        const float scale = 0.14433756729740643f;  // 48^-0.5
        int row = tid & 63, half = tid >> 6;
        const float* Srow = &sS[row * 68 + half * 32];
        float buf[32];
        float mx = -1e30f;
#pragma unroll
        for (int j = 0; j < 32; j++) { buf[j] = Srow[j] * scale; mx = fmaxf(mx, buf[j]); }
        red[tid] = mx;
        __syncthreads();
        mx = fmaxf(red[row], red[row + 64]);
        float sum = 0.0f;
#pragma unroll
        for (int j = 0; j < 32; j++) { buf[j] = __expf(buf[j] - mx); sum += buf[j]; }
        __syncthreads();
        red[tid] = sum;
        __syncthreads();
        float inv = 1.0f / (red[row] + red[row + 64]);
        __nv_bfloat16* Prow = &sP[row * 72 + half * 32];
#pragma unroll
        for (int j = 0; j < 32; j++) Prow[j] = __float2bfloat16(buf[j] * inv);
    }
    __syncthreads();

    {   // O = P @ V   [64x48], K=64
        wmma::fragment<wmma::accumulator, 16, 16, 16, float> acc[3];
#pragma unroll
        for (int j = 0; j < 3; j++) wmma::fill_fragment(acc[j], 0.0f);
#pragma unroll
        for (int k = 0; k < 64; k += 16) {
            wmma::fragment<wmma::matrix_a, 16, 16, 16, __nv_bfloat16, wmma::row_major> af;
            wmma::load_matrix_sync(af, &sP[m0 * 72 + k], 72);
#pragma unroll
            for (int j = 0; j < 3; j++) {
                wmma::fragment<wmma::matrix_b, 16, 16, 16, __nv_bfloat16, wmma::row_major> bf;
                wmma::load_matrix_sync(bf, &sv[k * 56 + j * 16], 56);
                wmma::mma_sync(acc[j], af, bf, acc[j]);
            }
        }
#pragma unroll
        for (int j = 0; j < 3; j++)
            wmma::store_matrix_sync(&sS[m0 * 68 + j * 16], acc[j], 68, wmma::mem_row_major);
    }
    __syncthreads();

    // write attn out as e4m3 (proj GEMM consumes fp8)
    uint8_t* dst = g_o + (size_t)win * 64 * 384 + head * 48;
    for (int li = tid; li < 64 * 12; li += 128) {
        int t = li / 12, g = li % 12;
        const float* sr = &sS[t * 68 + g * 4];
        *(uint32_t*)&dst[t * 384 + g * 4] = q4(sr[0], sr[1], sr[2], sr[3]);
    }
}

// ---------------- K8: depthwise 3x3 conv + bias + exact GELU (4 rows/block, fp8 out) ----------------
__global__ void __launch_bounds__(256) k_dwconv(const float* __restrict__ wgt,
                                                const float* __restrict__ bias) {
    __shared__ __nv_bfloat16 s[6 * 58 * 64];
    int b = blockIdx.y, h0 = blockIdx.x * 4;   // grid (14, 32)
    int tid = threadIdx.x;
    int c = tid & 63, sub = tid >> 6;

    for (int cc = 0; cc < HID; cc += 64) {
        __syncthreads();
        for (int li = tid; li < 6 * 58 * 8; li += 256) {
            int hr = li / 464;
            int rem = li % 464;
            int wi = rem >> 3;
            int grp = (rem & 7) * 8;
            int hh = h0 - 1 + hr, ww = wi - 1;
            uint4 val = make_uint4(0u, 0u, 0u, 0u);
            if (hh >= 0 && hh < HH_ && ww >= 0 && ww < WW_)
                val = *(const uint4*)&g_m1[((size_t)b * NS + hh * WW_ + ww) * HID + cc + grp];
            *(uint4*)&s[(hr * 58 + wi) * 64 + grp] = val;
        }
        __syncthreads();

        int ch = cc + c;
        float w9[9];
#pragma unroll
        for (int i = 0; i < 9; i++) w9[i] = wgt[ch * 9 + i];
        float bv = bias[ch];
        int h = h0 + sub;
        for (int w0 = 0; w0 < WW_; w0++) {
            float acc = bv;
#pragma unroll
            for (int dy = 0; dy < 3; dy++)
#pragma unroll
                for (int dx = 0; dx < 3; dx++)
                    acc += __bfloat162float(s[((sub + dy) * 58 + w0 + dx) * 64 + c]) * w9[dy * 3 + dx];
            float gl = 0.5f * acc * (1.0f + erff(acc * 0.70710678118f));
            g_mg[((size_t)b * NS + h * WW_ + w0) * HID + ch] = q1(gl);
        }
    }
}

// ---------------- launch ----------------
extern "C" void kernel_launch(void* const* d_in, const int* in_sizes, int n_in,
                              void* d_out, int out_size) {
    (void)in_sizes; (void)n_in; (void)out_size;
    const float* x      = (const float*)d_in[0];
    const float* ln1_g  = (const float*)d_in[1];
    const float* ln1_b  = (const float*)d_in[2];
    const float* qkv_w  = (const float*)d_in[3];
    const float* proj_w = (const float*)d_in[4];
    const float* proj_b = (const float*)d_in[5];
    const float* ln2_g  = (const float*)d_in[6];
    const float* ln2_b  = (const float*)d_in[7];
    const float* fc1_w  = (const float*)d_in[8];
    const float* fc1_b  = (const float*)d_in[9];
    const float* dw_w   = (const float*)d_in[10];
    const float* dw_b   = (const float*)d_in[11];
    const float* fc2_w  = (const float*)d_in[12];
    const float* fc2_b  = (const float*)d_in[13];
    const float* gamma1 = (const float*)d_in[14];
    const float* gamma2 = (const float*)d_in[15];
    float* out = (float*)d_out;

    // idempotent, deterministic, capture-safe
    cudaFuncSetAttribute(k_tln,     cudaFuncAttributeMaxDynamicSharedMemorySize, TLN_SMEM);
    cudaFuncSetAttribute(k_gemm<0>, cudaFuncAttributeMaxDynamicSharedMemorySize, GEMM_DSMEM);
    cudaFuncSetAttribute(k_gemm<1>, cudaFuncAttributeMaxDynamicSharedMemorySize, GEMM_DSMEM);
    cudaFuncSetAttribute(k_gemm<2>, cudaFuncAttributeMaxDynamicSharedMemorySize, GEMM_DSMEM);
    cudaFuncSetAttribute(k_gemm<3>, cudaFuncAttributeMaxDynamicSharedMemorySize, GEMM_DSMEM);

    k_wprepT<0><<<dim3(12, 36), dim3(32, 8)>>>(qkv_w);
    k_wprepT<1><<<dim3(12, 12), dim3(32, 8)>>>(proj_w);
    k_wprepT<2><<<dim3(12, 48), dim3(32, 8)>>>(fc1_w);
    k_wprepT<3><<<dim3(48, 12), dim3(32, 8)>>>(fc2_w);

    k_tln<<<dim3(NS / 32, BB), 256, TLN_SMEM>>>(x, ln1_g, ln1_b);
    k_gemm<0><<<dim3(1152 / 128, MR / 128), 256, GEMM_DSMEM>>>(nullptr, nullptr, nullptr);
    k_attn<<<dim3(NWIN, NHEADS), 128>>>();
    k_gemm<1><<<dim3(384 / 128, MR / 128), 256, GEMM_DSMEM>>>(proj_b, gamma1, nullptr);
    k_layernorm2<<<MR, 128>>>(ln2_g, ln2_b);
    k_gemm<2><<<dim3(1536 / 128, MR / 128), 256, GEMM_DSMEM>>>(fc1_b, nullptr, nullptr);
    k_dwconv<<<dim3(14, BB), 256>>>(dw_w, dw_b);
    k_gemm<3><<<dim3(384 / 128, MR / 128), 256, GEMM_DSMEM>>>(fc2_b, gamma2, out);
}

// round 14
// speedup vs baseline: 1.3362x; 1.0487x over previous
#include <cuda_runtime.h>
#include <cuda_bf16.h>
#include <cuda_fp8.h>
#include <mma.h>
#include <cstdint>

using namespace nvcuda;

// ---------------- problem constants ----------------
#define BB   32
#define CC_  384
#define HH_  56
#define WW_  56
#define NS   3136        // H*W
#define MR   100352      // B*N
#define HID  1536
#define NHEADS 8
#define HD   48
#define GG   7           // grid size
#define SSZ  8           // sparse size
#define NWIN 1568        // B*GG*GG
#define EPSV 1e-5f

// ---------------- scratch (device globals; allocation-free) ----------------
__device__ __align__(16) float          g_xT [(size_t)MR * CC_];       // [B,N,C] fp32
__device__ __align__(16) uint8_t        g_hln[(size_t)MR * CC_];       // LN1 out e4m3, window-major
__device__ __align__(16) __nv_bfloat16  g_qkv[(size_t)MR * 3 * CC_];   // window-major (bf16)
__device__ __align__(16) uint8_t        g_o  [(size_t)MR * CC_];       // attn out e4m3, window-major
__device__ __align__(16) float          g_x1 [(size_t)MR * CC_];       // residual1, token-major
__device__ __align__(16) uint8_t        g_ln2[(size_t)MR * CC_];       // LN2 out e4m3
__device__ __align__(16) uint8_t        g_m1 [(size_t)MR * HID];       // fc1 out e4m3
__device__ __align__(16) uint8_t        g_mg [(size_t)MR * HID];       // dwconv+gelu out e4m3
// fp8 weights, TRANSPOSED: [N, K] (K contiguous)
__device__ __align__(16) uint8_t        g_wq[(size_t)1152 * 384];
__device__ __align__(16) uint8_t        g_wp[(size_t)384 * 384];
__device__ __align__(16) uint8_t        g_w1[(size_t)1536 * 384];
__device__ __align__(16) uint8_t        g_w2[(size_t)384 * 1536];

// ---------------- fp8 helpers (consistent byte order everywhere) ----------------
__device__ __forceinline__ uint8_t q1(float v) {
    return (uint8_t)__nv_cvt_float_to_fp8(v, __NV_SATFINITE, __NV_E4M3);
}
__device__ __forceinline__ uint32_t q4(float v0, float v1, float v2, float v3) {
    return (uint32_t)q1(v0) | ((uint32_t)q1(v1) << 8) |
           ((uint32_t)q1(v2) << 16) | ((uint32_t)q1(v3) << 24);
}
__device__ __forceinline__ float d1(uint8_t b) {
    return __half2float(__nv_cvt_fp8_to_halfraw((__nv_fp8_storage_t)b, __NV_E4M3));
}
// 4 packed e4m3 -> 2 bf16x2 words
__device__ __forceinline__ uint2 d4_bf16(uint32_t p) {
    __nv_bfloat162 lo = __floats2bfloat162_rn(d1(p & 0xff), d1((p >> 8) & 0xff));
    __nv_bfloat162 hi = __floats2bfloat162_rn(d1((p >> 16) & 0xff), d1((p >> 24) & 0xff));
    return make_uint2(*(uint32_t*)&lo, *(uint32_t*)&hi);
}

__device__ __forceinline__ uint32_t sptr(const void* p) {
    uint32_t a;
    asm("{ .reg .u64 t; cvta.to.shared.u64 t, %1; cvt.u32.u64 %0, t; }" : "=r"(a) : "l"(p));
    return a;
}
__device__ __forceinline__ void ldsm4(uint32_t* r, uint32_t addr) {
    asm volatile("ldmatrix.sync.aligned.m8n8.x4.shared.b16 {%0,%1,%2,%3}, [%4];"
        : "=r"(r[0]), "=r"(r[1]), "=r"(r[2]), "=r"(r[3]) : "r"(addr));
}
__device__ __forceinline__ void mma_fp8(float* c, const uint32_t* a, const uint32_t* b) {
    asm volatile(
        "mma.sync.aligned.m16n8k32.row.col.f32.e4m3.e4m3.f32 "
        "{%0,%1,%2,%3}, {%4,%5,%6,%7}, {%8,%9}, {%0,%1,%2,%3};"
        : "+f"(c[0]), "+f"(c[1]), "+f"(c[2]), "+f"(c[3])
        : "r"(a[0]), "r"(a[1]), "r"(a[2]), "r"(a[3]), "r"(b[0]), "r"(b[1]));
}

// ---------------- K0: ALL weight transposes + fp8 quantize in ONE kernel ----------------
// linear block map: W0 432 blocks (12k x 36n) | W1 144 (12x12) | W2 576 (12x48) | W3 576 (48x12)
__global__ void k_wprep_all(const float* __restrict__ qkv_w, const float* __restrict__ proj_w,
                            const float* __restrict__ fc1_w, const float* __restrict__ fc2_w) {
    __shared__ float t[32][33];
    int id = blockIdx.x;
    const float* W; uint8_t* Wt; int K, N, kb, nb2;
    if (id < 432)       { W = qkv_w;  Wt = g_wq; K = 384;  N = 1152; kb = id % 12;          nb2 = id / 12; }
    else if (id < 576)  { W = proj_w; Wt = g_wp; K = 384;  N = 384;  kb = (id - 432) % 12;  nb2 = (id - 432) / 12; }
    else if (id < 1152) { W = fc1_w;  Wt = g_w1; K = 384;  N = 1536; kb = (id - 576) % 12;  nb2 = (id - 576) / 12; }
    else                { W = fc2_w;  Wt = g_w2; K = 1536; N = 384;  kb = (id - 1152) % 48; nb2 = (id - 1152) / 48; }
    int k0 = kb * 32, nb = nb2 * 32;
    int tx = threadIdx.x, ty = threadIdx.y;   // (32,8)
#pragma unroll
    for (int i = 0; i < 32; i += 8)
        t[ty + i][tx] = W[(size_t)(k0 + ty + i) * N + nb + tx];
    __syncthreads();
#pragma unroll
    for (int i = 0; i < 32; i += 8)
        Wt[(size_t)(nb + ty + i) * K + k0 + tx] = q1(t[tx][ty + i]);
}

// ---------------- K1: FUSED NCHW transpose + LN1 + window gather (fp8 out) ----------------
#define TLN_SMEM (384 * 33 * 4)
__global__ void __launch_bounds__(256) k_tln(const float* __restrict__ x,
                                             const float* __restrict__ gam,
                                             const float* __restrict__ bet) {
    extern __shared__ float tl[];
    int b = blockIdx.y, n0 = blockIdx.x * 32;
    int tid = threadIdx.x;
    const float* xb = x + (size_t)b * CC_ * NS;
    for (int i = tid; i < 384 * 8; i += 256) {
        int c = i >> 3, v = i & 7;
        float4 f = *(const float4*)&xb[(size_t)c * NS + n0 + v * 4];
        float* d = &tl[c * 33 + v * 4];
        d[0] = f.x; d[1] = f.y; d[2] = f.z; d[3] = f.w;
    }
    __syncthreads();
    int t = tid >> 3, p = tid & 7;     // token t (0..31), part p: channels [p*48, +48)
    int n = n0 + t;
    float s = 0.0f, sq = 0.0f;
#pragma unroll
    for (int j = 0; j < 48; j++) {
        float v = tl[(p * 48 + j) * 33 + t];
        s += v; sq += v * v;
    }
#pragma unroll
    for (int o = 4; o; o >>= 1) {
        s  += __shfl_xor_sync(0xffffffffu, s,  o);
        sq += __shfl_xor_sync(0xffffffffu, sq, o);
    }
    float mean = s * (1.0f / CC_);
    float var  = sq * (1.0f / CC_) - mean * mean;
    float rstd = rsqrtf(var + EPSV);

    int h = n / WW_, wpos = n % WW_;
    int gi = h % GG, si = h / GG;
    int gj = wpos % GG, sj = wpos / GG;
    size_t orow = ((size_t)((b * GG + gi) * GG + gj)) * 64 + si * SSZ + sj;
    float*   xt = g_xT  + ((size_t)b * NS + n) * CC_;
    uint8_t* hl = g_hln + orow * CC_;
#pragma unroll
    for (int j4 = 0; j4 < 48; j4 += 4) {
        int c = p * 48 + j4;
        float v0 = tl[(c + 0) * 33 + t], v1 = tl[(c + 1) * 33 + t];
        float v2 = tl[(c + 2) * 33 + t], v3 = tl[(c + 3) * 33 + t];
        *(float4*)&xt[c] = make_float4(v0, v1, v2, v3);
        *(uint32_t*)&hl[c] = q4((v0 - mean) * rstd * gam[c + 0] + bet[c + 0],
                                (v1 - mean) * rstd * gam[c + 1] + bet[c + 1],
                                (v2 - mean) * rstd * gam[c + 2] + bet[c + 2],
                                (v3 - mean) * rstd * gam[c + 3] + bet[c + 3]);
    }
}

// ---------------- K6: LayerNorm 2 (token-major, fp8 out) ----------------
__global__ void k_layernorm2(const float* __restrict__ gam, const float* __restrict__ bet) {
    int r   = blockIdx.x;
    int tid = threadIdx.x;          // 128
    const float* src = g_x1 + (size_t)r * CC_;
    float v0 = src[tid], v1 = src[tid + 128], v2 = src[tid + 256];
    float s  = v0 + v1 + v2;
    float sq = v0 * v0 + v1 * v1 + v2 * v2;
#pragma unroll
    for (int o = 16; o; o >>= 1) {
        s  += __shfl_xor_sync(0xffffffffu, s,  o);
        sq += __shfl_xor_sync(0xffffffffu, sq, o);
    }
    __shared__ float ws[4], wq[4];
    int w = tid >> 5, l = tid & 31;
    if (l == 0) { ws[w] = s; wq[w] = sq; }
    __syncthreads();
    float mean = (ws[0] + ws[1] + ws[2] + ws[3]) * (1.0f / CC_);
    float var  = (wq[0] + wq[1] + wq[2] + wq[3]) * (1.0f / CC_) - mean * mean;
    float rstd = rsqrtf(var + EPSV);
    uint8_t* dst = g_ln2 + (size_t)r * CC_;
    dst[tid]       = q1((v0 - mean) * rstd * gam[tid]       + bet[tid]);
    dst[tid + 128] = q1((v1 - mean) * rstd * gam[tid + 128] + bet[tid + 128]);
    dst[tid + 256] = q1((v2 - mean) * rstd * gam[tid + 256] + bet[tid + 256]);
}

// ---------------- FP8 GEMM: 128x128 CTA, 32x64 warp tile, K-tile 128B, 2-stage ----------------
// 8 warps 4(M) x 2(N). mma.m16n8k32 e4m3; A [M,K] fp8, B [N,K] fp8 (both K-contig).
// smem rows 144B (128 data + 16 pad): ldmatrix rows 4 banks apart, conflict-free.
// stage = A 128x144 + B 128x144 = 36864 B; 2 stages = 73728 B; 2 CTAs/SM (146 KB < 228 KB).
// MODE 0: QKV   A=g_hln  K=384  N=1152 -> g_qkv (bf16)
// MODE 1: PROJ  A=g_o    K=384  N=384  -> g_x1 = xT + gamma1*(A@W + b)  (window->token scatter)
// MODE 2: FC1   A=g_ln2  K=384  N=1536 -> g_m1 = e4m3(A@W + b)
// MODE 3: FC2   A=g_mg   K=1536 N=384  -> out[b,c,n] = x1 + gamma2*(A@W + b)  (NCHW permute)
#define STG_BYTES 36864
#define GEMM_DSMEM (2 * STG_BYTES)

template<int MODE>
__global__ void __launch_bounds__(256, 2) k_gemm(
    const float* __restrict__ bias, const float* __restrict__ gamma,
    float* __restrict__ outp)
{
    constexpr int Kdim  = (MODE == 3) ? 1536 : 384;
    constexpr int Ncols = (MODE == 0) ? 1152 : ((MODE == 2) ? 1536 : 384);
    constexpr int NKT   = Kdim / 128;

    const uint8_t* A  = (MODE == 0) ? g_hln : (MODE == 1) ? g_o : (MODE == 2) ? g_ln2 : g_mg;
    const uint8_t* Bw = (MODE == 0) ? g_wq  : (MODE == 1) ? g_wp : (MODE == 2) ? g_w1 : g_w2;

    extern __shared__ __align__(16) char dsm[];
    uint32_t dbase = sptr(dsm);

    int n0 = blockIdx.x * 128;
    int m0 = blockIdx.y * 128;
    int tid  = threadIdx.x;
    int warp = tid >> 5, lane = tid & 31;
    int wm = warp & 3, wn = warp >> 2;   // warp tile rows [wm*32,+32), cols [wn*64,+64)

    float acc[2][8][4];
#pragma unroll
    for (int i = 0; i < 2; i++)
#pragma unroll
        for (int j = 0; j < 8; j++)
#pragma unroll
            for (int q = 0; q < 4; q++) acc[i][j][q] = 0.0f;

    // stage: A at st (128 rows x 144B), B at st+18432 (128 n-rows x 144B); 128B data/row
    auto load_stage = [&](int kt, int buf) {
        int k0 = kt * 128;
        uint32_t st = dbase + buf * STG_BYTES;
#pragma unroll
        for (int s = 0; s < 8; s++) {
            int i = tid + s * 256;
            uint32_t dst; const uint8_t* src;
            if (i < 1024) {          // A: 128 rows x 8 chunks of 16B
                int r = i >> 3, c = i & 7;
                dst = st + r * 144 + c * 16;
                src = A + (size_t)(m0 + r) * Kdim + k0 + c * 16;
            } else {                 // B: 128 n-rows x 8 chunks of 16B
                int j = i - 1024, r = j >> 3, c = j & 7;
                dst = st + 18432 + r * 144 + c * 16;
                src = Bw + (size_t)(n0 + r) * Kdim + k0 + c * 16;
            }
            asm volatile("cp.async.cg.shared.global [%0], [%1], 16;" :: "r"(dst), "l"(src));
        }
        asm volatile("cp.async.commit_group;" ::: "memory");
    };

    load_stage(0, 0);

    int lrow = lane & 15, lhi = lane >> 4;
    for (int kt = 0; kt < NKT; ++kt) {
        int buf = kt & 1;
        if (kt + 1 < NKT) load_stage(kt + 1, buf ^ 1);
        else asm volatile("cp.async.commit_group;" ::: "memory");
        asm volatile("cp.async.wait_group 1;" ::: "memory");
        __syncthreads();

        uint32_t stA = dbase + buf * STG_BYTES;
        uint32_t stB = stA + 18432;
#pragma unroll
        for (int h = 0; h < 4; h++) {           // four k=32 steps per 128B tile
            uint32_t a[2][4], b[8][2];
#pragma unroll
            for (int i = 0; i < 2; i++)
                ldsm4(a[i], stA + (wm * 32 + i * 16 + lrow) * 144 + (h * 2 + lhi) * 16);
#pragma unroll
            for (int jp = 0; jp < 4; jp++) {
                uint32_t t4[4];
                ldsm4(t4, stB + (wn * 64 + jp * 16 + lrow) * 144 + (h * 2 + lhi) * 16);
                b[2 * jp][0] = t4[0];  b[2 * jp][1] = t4[2];
                b[2 * jp + 1][0] = t4[1]; b[2 * jp + 1][1] = t4[3];
            }
#pragma unroll
            for (int i = 0; i < 2; i++)
#pragma unroll
                for (int j = 0; j < 8; j++)
                    mma_fp8(acc[i][j], a[i], b[j]);
        }
        __syncthreads();
    }

    // ---------------- epilogue: 2 passes; warp stages 16x64 fp32 (16x68 padded) ----------------
    float* sEpi = (float*)dsm + warp * 1088;     // 16*68 floats = 4352 B/warp; 8 warps = 34816 B
    int row0 = lane >> 2, col0 = 2 * (lane & 3);

#pragma unroll
    for (int i = 0; i < 2; i++) {
#pragma unroll
        for (int j = 0; j < 8; j++) {
            sEpi[row0 * 68 + 8 * j + col0]           = acc[i][j][0];
            sEpi[row0 * 68 + 8 * j + col0 + 1]       = acc[i][j][1];
            sEpi[(row0 + 8) * 68 + 8 * j + col0]     = acc[i][j][2];
            sEpi[(row0 + 8) * 68 + 8 * j + col0 + 1] = acc[i][j][3];
        }
        __syncwarp();
        int growb = m0 + wm * 32 + i * 16;
        int gcolb = n0 + wn * 64;
#pragma unroll
        for (int e = 0; e < 32; e++) {
            int idx = e * 32 + lane;
            int rr, cc;
            if (MODE == 3) { cc = idx >> 4; rr = idx & 15; }     // column-major: coalesced over n
            else           { rr = idx >> 6; cc = idx & 63; }
            float v = sEpi[rr * 68 + cc];
            int grow = growb + rr, gcol = gcolb + cc;
            if (MODE == 0) {
                g_qkv[(size_t)grow * Ncols + gcol] = __float2bfloat16(v);
            } else if (MODE == 2) {
                g_m1[(size_t)grow * Ncols + gcol] = q1(v + bias[gcol]);
            } else if (MODE == 1) {
                int win = grow >> 6, t = grow & 63;
                int b = win / 49, wi = win % 49;
                int gi = wi / 7, gj = wi % 7;
                int si = t >> 3, sj = t & 7;
                int h = si * GG + gi, wp = sj * GG + gj;
                size_t ridx = ((size_t)b * NS + h * WW_ + wp) * CC_ + gcol;
                g_x1[ridx] = g_xT[ridx] + gamma[gcol] * (v + bias[gcol]);
            } else {  // MODE 3
                int b = grow / NS, n = grow % NS;
                float ov = g_x1[(size_t)grow * CC_ + gcol]
                         + gamma[gcol] * (v + bias[gcol]);
                outp[((size_t)b * CC_ + gcol) * NS + n] = ov;
            }
        }
        __syncwarp();
    }
}

// ---------------- K4: attention, one block per (window, head), 4 warps ----------------
__global__ void __launch_bounds__(128) k_attn() {
    int win  = blockIdx.x;
    int head = blockIdx.y;
    __shared__ __nv_bfloat16 sq[64 * 56], sk[64 * 56], sv[64 * 56];
    __shared__ float sS[64 * 68];
    __shared__ __nv_bfloat16 sP[64 * 72];
    __shared__ float red[128];
    int tid = threadIdx.x;

    size_t base = (size_t)win * 64 * 1152;
#pragma unroll
    for (int m = 0; m < 3; m++) {
        const __nv_bfloat16* src = g_qkv + base + m * 384 + head * 48;
        __nv_bfloat16* dst = (m == 0) ? sq : (m == 1) ? sk : sv;
        for (int li = tid; li < 64 * 6; li += 128) {
            int t = li / 6, dg = (li % 6) * 8;
            *(uint4*)&dst[t * 56 + dg] = *(const uint4*)&src[(size_t)t * 1152 + dg];
        }
    }
    __syncthreads();

    int warp = tid >> 5;
    int m0 = warp * 16;
    {   // S = q @ k^T   [64x64], K=48
        wmma::fragment<wmma::accumulator, 16, 16, 16, float> acc[4];
#pragma unroll
        for (int j = 0; j < 4; j++) wmma::fill_fragment(acc[j], 0.0f);
#pragma unroll
        for (int k = 0; k < 48; k += 16) {
            wmma::fragment<wmma::matrix_a, 16, 16, 16, __nv_bfloat16, wmma::row_major> af;
            wmma::load_matrix_sync(af, &sq[m0 * 56 + k], 56);
#pragma unroll
            for (int j = 0; j < 4; j++) {
                wmma::fragment<wmma::matrix_b, 16, 16, 16, __nv_bfloat16, wmma::col_major> bf;
                wmma::load_matrix_sync(bf, &sk[(j * 16) * 56 + k], 56);
                wmma::mma_sync(acc[j], af, bf, acc[j]);
            }
        }
#pragma unroll
        for (int j = 0; j < 4; j++)
            wmma::store_matrix_sync(&sS[m0 * 68 + j * 16], acc[j], 68, wmma::mem_row_major);
    }
    __syncthreads();

    {   // softmax: 128 threads, 2 per row, smem combine
        const float scale = 0.14433756729740643f;  // 48^-0.5
        int row = tid & 63, half = tid >> 6;
        const float* Srow = &sS[row * 68 + half * 32];
        float buf[32];
        float mx = -1e30f;
#pragma unroll
        for (int j = 0; j < 32; j++) { buf[j] = Srow[j] * scale; mx = fmaxf(mx, buf[j]); }
        red[tid] = mx;
        __syncthreads();
        mx = fmaxf(red[row], red[row + 64]);
        float sum = 0.0f;
#pragma unroll
        for (int j = 0; j < 32; j++) { buf[j] = __expf(buf[j] - mx); sum += buf[j]; }
        __syncthreads();
        red[tid] = sum;
        __syncthreads();
        float inv = 1.0f / (red[row] + red[row + 64]);
        __nv_bfloat16* Prow = &sP[row * 72 + half * 32];
#pragma unroll
        for (int j = 0; j < 32; j++) Prow[j] = __float2bfloat16(buf[j] * inv);
    }
    __syncthreads();

    {   // O = P @ V   [64x48], K=64
        wmma::fragment<wmma::accumulator, 16, 16, 16, float> acc[3];
#pragma unroll
        for (int j = 0; j < 3; j++) wmma::fill_fragment(acc[j], 0.0f);
#pragma unroll
        for (int k = 0; k < 64; k += 16) {
            wmma::fragment<wmma::matrix_a, 16, 16, 16, __nv_bfloat16, wmma::row_major> af;
            wmma::load_matrix_sync(af, &sP[m0 * 72 + k], 72);
#pragma unroll
            for (int j = 0; j < 3; j++) {
                wmma::fragment<wmma::matrix_b, 16, 16, 16, __nv_bfloat16, wmma::row_major> bf;
                wmma::load_matrix_sync(bf, &sv[k * 56 + j * 16], 56);
                wmma::mma_sync(acc[j], af, bf, acc[j]);
            }
        }
#pragma unroll
        for (int j = 0; j < 3; j++)
            wmma::store_matrix_sync(&sS[m0 * 68 + j * 16], acc[j], 68, wmma::mem_row_major);
    }
    __syncthreads();

    // write attn out as e4m3 (proj GEMM consumes fp8)
    uint8_t* dst = g_o + (size_t)win * 64 * 384 + head * 48;
    for (int li = tid; li < 64 * 12; li += 128) {
        int t = li / 12, g = li % 12;
        const float* sr = &sS[t * 68 + g * 4];
        *(uint32_t*)&dst[t * 384 + g * 4] = q4(sr[0], sr[1], sr[2], sr[3]);
    }
}

// ---------------- K8: depthwise 3x3 conv + bias + exact GELU (4 rows/block, fp8 in/out) ----------------
__global__ void __launch_bounds__(256) k_dwconv(const float* __restrict__ wgt,
                                                const float* __restrict__ bias) {
    __shared__ __nv_bfloat16 s[6 * 58 * 64];
    int b = blockIdx.y, h0 = blockIdx.x * 4;   // grid (14, 32)
    int tid = threadIdx.x;
    int c = tid & 63, sub = tid >> 6;

    for (int cc = 0; cc < HID; cc += 64) {
        __syncthreads();
        for (int li = tid; li < 6 * 58 * 8; li += 256) {
            int hr = li / 464;
            int rem = li % 464;
            int wi = rem >> 3;
            int grp = (rem & 7) * 8;
            int hh = h0 - 1 + hr, ww = wi - 1;
            uint2 v8 = make_uint2(0u, 0u);      // 8 fp8 elems
            if (hh >= 0 && hh < HH_ && ww >= 0 && ww < WW_)
                v8 = *(const uint2*)&g_m1[((size_t)b * NS + hh * WW_ + ww) * HID + cc + grp];
            uint2 lo = d4_bf16(v8.x), hi = d4_bf16(v8.y);
            *(uint4*)&s[(hr * 58 + wi) * 64 + grp] = make_uint4(lo.x, lo.y, hi.x, hi.y);
        }
        __syncthreads();

        int ch = cc + c;
        float w9[9];
#pragma unroll
        for (int i = 0; i < 9; i++) w9[i] = wgt[ch * 9 + i];
        float bv = bias[ch];
        int h = h0 + sub;
        for (int w0 = 0; w0 < WW_; w0++) {
            float acc = bv;
#pragma unroll
            for (int dy = 0; dy < 3; dy++)
#pragma unroll
                for (int dx = 0; dx < 3; dx++)
                    acc += __bfloat162float(s[((sub + dy) * 58 + w0 + dx) * 64 + c]) * w9[dy * 3 + dx];
            float gl = 0.5f * acc * (1.0f + erff(acc * 0.70710678118f));
            g_mg[((size_t)b * NS + h * WW_ + w0) * HID + ch] = q1(gl);
        }
    }
}

// ---------------- launch ----------------
extern "C" void kernel_launch(void* const* d_in, const int* in_sizes, int n_in,
                              void* d_out, int out_size) {
    (void)in_sizes; (void)n_in; (void)out_size;
    const float* x      = (const float*)d_in[0];
    const float* ln1_g  = (const float*)d_in[1];
    const float* ln1_b  = (const float*)d_in[2];
    const float* qkv_w  = (const float*)d_in[3];
    const float* proj_w = (const float*)d_in[4];
    const float* proj_b = (const float*)d_in[5];
    const float* ln2_g  = (const float*)d_in[6];
    const float* ln2_b  = (const float*)d_in[7];
    const float* fc1_w  = (const float*)d_in[8];
    const float* fc1_b  = (const float*)d_in[9];
    const float* dw_w   = (const float*)d_in[10];
    const float* dw_b   = (const float*)d_in[11];
    const float* fc2_w  = (const float*)d_in[12];
    const float* fc2_b  = (const float*)d_in[13];
    const float* gamma1 = (const float*)d_in[14];
    const float* gamma2 = (const float*)d_in[15];
    float* out = (float*)d_out;

    // idempotent, deterministic, capture-safe
    cudaFuncSetAttribute(k_tln,     cudaFuncAttributeMaxDynamicSharedMemorySize, TLN_SMEM);
    cudaFuncSetAttribute(k_gemm<0>, cudaFuncAttributeMaxDynamicSharedMemorySize, GEMM_DSMEM);
    cudaFuncSetAttribute(k_gemm<1>, cudaFuncAttributeMaxDynamicSharedMemorySize, GEMM_DSMEM);
    cudaFuncSetAttribute(k_gemm<2>, cudaFuncAttributeMaxDynamicSharedMemorySize, GEMM_DSMEM);
    cudaFuncSetAttribute(k_gemm<3>, cudaFuncAttributeMaxDynamicSharedMemorySize, GEMM_DSMEM);

    k_wprep_all<<<1728, dim3(32, 8)>>>(qkv_w, proj_w, fc1_w, fc2_w);
    k_tln<<<dim3(NS / 32, BB), 256, TLN_SMEM>>>(x, ln1_g, ln1_b);
    k_gemm<0><<<dim3(1152 / 128, MR / 128), 256, GEMM_DSMEM>>>(nullptr, nullptr, nullptr);
    k_attn<<<dim3(NWIN, NHEADS), 128>>>();
    k_gemm<1><<<dim3(384 / 128, MR / 128), 256, GEMM_DSMEM>>>(proj_b, gamma1, nullptr);
    k_layernorm2<<<MR, 128>>>(ln2_g, ln2_b);
    k_gemm<2><<<dim3(1536 / 128, MR / 128), 256, GEMM_DSMEM>>>(fc1_b, nullptr, nullptr);
    k_dwconv<<<dim3(14, BB), 256>>>(dw_w, dw_b);
    k_gemm<3><<<dim3(384 / 128, MR / 128), 256, GEMM_DSMEM>>>(fc2_b, gamma2, out);
}

// round 16
// speedup vs baseline: 1.4080x; 1.0538x over previous
#include <cuda_runtime.h>
#include <cuda_bf16.h>
#include <cuda_fp8.h>
#include <cstdint>

// ---------------- problem constants ----------------
#define BB   32
#define CC_  384
#define HH_  56
#define WW_  56
#define NS   3136        // H*W
#define MR   100352      // B*N
#define HID  1536
#define NHEADS 8
#define HD   48
#define GG   7           // grid size
#define SSZ  8           // sparse size
#define NWIN 1568        // B*GG*GG
#define EPSV 1e-5f

// ---------------- scratch (device globals; allocation-free) ----------------
__device__ __align__(16) float          g_xT [(size_t)MR * CC_];       // [B,N,C] fp32
__device__ __align__(16) uint8_t        g_hln[(size_t)MR * CC_];       // LN1 out e4m3, window-major
__device__ __align__(16) uint8_t        g_qkv[(size_t)MR * 3 * CC_];   // window-major e4m3
__device__ __align__(16) uint8_t        g_o  [(size_t)MR * CC_];       // attn out e4m3, window-major
__device__ __align__(16) float          g_x1 [(size_t)MR * CC_];       // residual1, token-major
__device__ __align__(16) uint8_t        g_ln2[(size_t)MR * CC_];       // LN2 out e4m3
__device__ __align__(16) uint8_t        g_m1 [(size_t)MR * HID];       // fc1 out e4m3
__device__ __align__(16) uint8_t        g_mg [(size_t)MR * HID];       // dwconv+gelu out e4m3
// fp8 weights, TRANSPOSED: [N, K] (K contiguous)
__device__ __align__(16) uint8_t        g_wq[(size_t)1152 * 384];
__device__ __align__(16) uint8_t        g_wp[(size_t)384 * 384];
__device__ __align__(16) uint8_t        g_w1[(size_t)1536 * 384];
__device__ __align__(16) uint8_t        g_w2[(size_t)384 * 1536];

// ---------------- fp8 helpers (consistent byte order everywhere) ----------------
__device__ __forceinline__ uint8_t q1(float v) {
    return (uint8_t)__nv_cvt_float_to_fp8(v, __NV_SATFINITE, __NV_E4M3);
}
__device__ __forceinline__ uint32_t q4(float v0, float v1, float v2, float v3) {
    return (uint32_t)q1(v0) | ((uint32_t)q1(v1) << 8) |
           ((uint32_t)q1(v2) << 16) | ((uint32_t)q1(v3) << 24);
}
__device__ __forceinline__ float d1(uint8_t b) {
    return __half2float(__nv_cvt_fp8_to_halfraw((__nv_fp8_storage_t)b, __NV_E4M3));
}
__device__ __forceinline__ uint2 d4_bf16(uint32_t p) {
    __nv_bfloat162 lo = __floats2bfloat162_rn(d1(p & 0xff), d1((p >> 8) & 0xff));
    __nv_bfloat162 hi = __floats2bfloat162_rn(d1((p >> 16) & 0xff), d1((p >> 24) & 0xff));
    return make_uint2(*(uint32_t*)&lo, *(uint32_t*)&hi);
}

__device__ __forceinline__ uint32_t sptr(const void* p) {
    uint32_t a;
    asm("{ .reg .u64 t; cvta.to.shared.u64 t, %1; cvt.u32.u64 %0, t; }" : "=r"(a) : "l"(p));
    return a;
}
__device__ __forceinline__ void ldsm4(uint32_t* r, uint32_t addr) {
    asm volatile("ldmatrix.sync.aligned.m8n8.x4.shared.b16 {%0,%1,%2,%3}, [%4];"
        : "=r"(r[0]), "=r"(r[1]), "=r"(r[2]), "=r"(r[3]) : "r"(addr));
}
__device__ __forceinline__ void mma_fp8(float* c, const uint32_t* a, const uint32_t* b) {
    asm volatile(
        "mma.sync.aligned.m16n8k32.row.col.f32.e4m3.e4m3.f32 "
        "{%0,%1,%2,%3}, {%4,%5,%6,%7}, {%8,%9}, {%0,%1,%2,%3};"
        : "+f"(c[0]), "+f"(c[1]), "+f"(c[2]), "+f"(c[3])
        : "r"(a[0]), "r"(a[1]), "r"(a[2]), "r"(a[3]), "r"(b[0]), "r"(b[1]));
}

// ---------------- K0: ALL weight transposes + fp8 quantize in ONE kernel ----------------
__global__ void k_wprep_all(const float* __restrict__ qkv_w, const float* __restrict__ proj_w,
                            const float* __restrict__ fc1_w, const float* __restrict__ fc2_w) {
    __shared__ float t[32][33];
    int id = blockIdx.x;
    const float* W; uint8_t* Wt; int K, N, kb, nb2;
    if (id < 432)       { W = qkv_w;  Wt = g_wq; K = 384;  N = 1152; kb = id % 12;          nb2 = id / 12; }
    else if (id < 576)  { W = proj_w; Wt = g_wp; K = 384;  N = 384;  kb = (id - 432) % 12;  nb2 = (id - 432) / 12; }
    else if (id < 1152) { W = fc1_w;  Wt = g_w1; K = 384;  N = 1536; kb = (id - 576) % 12;  nb2 = (id - 576) / 12; }
    else                { W = fc2_w;  Wt = g_w2; K = 1536; N = 384;  kb = (id - 1152) % 48; nb2 = (id - 1152) / 48; }
    int k0 = kb * 32, nb = nb2 * 32;
    int tx = threadIdx.x, ty = threadIdx.y;   // (32,8)
#pragma unroll
    for (int i = 0; i < 32; i += 8)
        t[ty + i][tx] = W[(size_t)(k0 + ty + i) * N + nb + tx];
    __syncthreads();
#pragma unroll
    for (int i = 0; i < 32; i += 8)
        Wt[(size_t)(nb + ty + i) * K + k0 + tx] = q1(t[tx][ty + i]);
}

// ---------------- K1: FUSED NCHW transpose + LN1 + window gather (fp8 out) ----------------
#define TLN_SMEM (384 * 33 * 4)
__global__ void __launch_bounds__(256) k_tln(const float* __restrict__ x,
                                             const float* __restrict__ gam,
                                             const float* __restrict__ bet) {
    extern __shared__ float tl[];
    int b = blockIdx.y, n0 = blockIdx.x * 32;
    int tid = threadIdx.x;
    const float* xb = x + (size_t)b * CC_ * NS;
    for (int i = tid; i < 384 * 8; i += 256) {
        int c = i >> 3, v = i & 7;
        float4 f = *(const float4*)&xb[(size_t)c * NS + n0 + v * 4];
        float* d = &tl[c * 33 + v * 4];
        d[0] = f.x; d[1] = f.y; d[2] = f.z; d[3] = f.w;
    }
    __syncthreads();
    int t = tid >> 3, p = tid & 7;
    int n = n0 + t;
    float s = 0.0f, sq = 0.0f;
#pragma unroll
    for (int j = 0; j < 48; j++) {
        float v = tl[(p * 48 + j) * 33 + t];
        s += v; sq += v * v;
    }
#pragma unroll
    for (int o = 4; o; o >>= 1) {
        s  += __shfl_xor_sync(0xffffffffu, s,  o);
        sq += __shfl_xor_sync(0xffffffffu, sq, o);
    }
    float mean = s * (1.0f / CC_);
    float var  = sq * (1.0f / CC_) - mean * mean;
    float rstd = rsqrtf(var + EPSV);

    int h = n / WW_, wpos = n % WW_;
    int gi = h % GG, si = h / GG;
    int gj = wpos % GG, sj = wpos / GG;
    size_t orow = ((size_t)((b * GG + gi) * GG + gj)) * 64 + si * SSZ + sj;
    float*   xt = g_xT  + ((size_t)b * NS + n) * CC_;
    uint8_t* hl = g_hln + orow * CC_;
#pragma unroll
    for (int j4 = 0; j4 < 48; j4 += 4) {
        int c = p * 48 + j4;
        float v0 = tl[(c + 0) * 33 + t], v1 = tl[(c + 1) * 33 + t];
        float v2 = tl[(c + 2) * 33 + t], v3 = tl[(c + 3) * 33 + t];
        *(float4*)&xt[c] = make_float4(v0, v1, v2, v3);
        *(uint32_t*)&hl[c] = q4((v0 - mean) * rstd * gam[c + 0] + bet[c + 0],
                                (v1 - mean) * rstd * gam[c + 1] + bet[c + 1],
                                (v2 - mean) * rstd * gam[c + 2] + bet[c + 2],
                                (v3 - mean) * rstd * gam[c + 3] + bet[c + 3]);
    }
}

// ---------------- K6: LayerNorm 2 (token-major, fp8 out) ----------------
__global__ void k_layernorm2(const float* __restrict__ gam, const float* __restrict__ bet) {
    int r   = blockIdx.x;
    int tid = threadIdx.x;          // 128
    const float* src = g_x1 + (size_t)r * CC_;
    float v0 = src[tid], v1 = src[tid + 128], v2 = src[tid + 256];
    float s  = v0 + v1 + v2;
    float sq = v0 * v0 + v1 * v1 + v2 * v2;
#pragma unroll
    for (int o = 16; o; o >>= 1) {
        s  += __shfl_xor_sync(0xffffffffu, s,  o);
        sq += __shfl_xor_sync(0xffffffffu, sq, o);
    }
    __shared__ float ws[4], wq[4];
    int w = tid >> 5, l = tid & 31;
    if (l == 0) { ws[w] = s; wq[w] = sq; }
    __syncthreads();
    float mean = (ws[0] + ws[1] + ws[2] + ws[3]) * (1.0f / CC_);
    float var  = (wq[0] + wq[1] + wq[2] + wq[3]) * (1.0f / CC_) - mean * mean;
    float rstd = rsqrtf(var + EPSV);
    uint8_t* dst = g_ln2 + (size_t)r * CC_;
    dst[tid]       = q1((v0 - mean) * rstd * gam[tid]       + bet[tid]);
    dst[tid + 128] = q1((v1 - mean) * rstd * gam[tid + 128] + bet[tid + 128]);
    dst[tid + 256] = q1((v2 - mean) * rstd * gam[tid + 256] + bet[tid + 256]);
}

// ---------------- FP8 GEMM: 128x128 CTA, 32x64 warp tile, K-tile 128B, 3-stage ----------------
// ONE __syncthreads per K-iter: order = wait(1) -> sync -> load(kt+2) -> compute(kt).
// Sync guarantees all threads finished compute kt-1 (which read buf (kt-1)%3 == (kt+2)%3)
// before anyone cp.asyncs into it.  stage = 2 x 128 x 144 = 36864 B; 3 stages = 110592 B.
// MODE 0: QKV   A=g_hln  K=384  N=1152 -> g_qkv (e4m3)
// MODE 1: PROJ  A=g_o    K=384  N=384  -> g_x1 = xT + gamma1*(A@W + b)  (window->token scatter)
// MODE 2: FC1   A=g_ln2  K=384  N=1536 -> g_m1 = e4m3(A@W + b)
// MODE 3: FC2   A=g_mg   K=1536 N=384  -> out[b,c,n] = x1 + gamma2*(A@W + b)  (NCHW permute)
#define STG_BYTES 36864
#define GEMM_DSMEM (3 * STG_BYTES)

template<int MODE>
__global__ void __launch_bounds__(256, 2) k_gemm(
    const float* __restrict__ bias, const float* __restrict__ gamma,
    float* __restrict__ outp)
{
    constexpr int Kdim  = (MODE == 3) ? 1536 : 384;
    constexpr int Ncols = (MODE == 0) ? 1152 : ((MODE == 2) ? 1536 : 384);
    constexpr int NKT   = Kdim / 128;

    const uint8_t* A  = (MODE == 0) ? g_hln : (MODE == 1) ? g_o : (MODE == 2) ? g_ln2 : g_mg;
    const uint8_t* Bw = (MODE == 0) ? g_wq  : (MODE == 1) ? g_wp : (MODE == 2) ? g_w1 : g_w2;

    extern __shared__ __align__(16) char dsm[];
    uint32_t dbase = sptr(dsm);

    int n0 = blockIdx.x * 128;
    int m0 = blockIdx.y * 128;
    int tid  = threadIdx.x;
    int warp = tid >> 5, lane = tid & 31;
    int wm = warp & 3, wn = warp >> 2;

    float acc[2][8][4];
#pragma unroll
    for (int i = 0; i < 2; i++)
#pragma unroll
        for (int j = 0; j < 8; j++)
#pragma unroll
            for (int q = 0; q < 4; q++) acc[i][j][q] = 0.0f;

    auto load_stage = [&](int kt, int buf) {
        int k0 = kt * 128;
        uint32_t st = dbase + buf * STG_BYTES;
#pragma unroll
        for (int s = 0; s < 8; s++) {
            int i = tid + s * 256;
            uint32_t dst; const uint8_t* src;
            if (i < 1024) {
                int r = i >> 3, c = i & 7;
                dst = st + r * 144 + c * 16;
                src = A + (size_t)(m0 + r) * Kdim + k0 + c * 16;
            } else {
                int j = i - 1024, r = j >> 3, c = j & 7;
                dst = st + 18432 + r * 144 + c * 16;
                src = Bw + (size_t)(n0 + r) * Kdim + k0 + c * 16;
            }
            asm volatile("cp.async.cg.shared.global [%0], [%1], 16;" :: "r"(dst), "l"(src));
        }
        asm volatile("cp.async.commit_group;" ::: "memory");
    };

    load_stage(0, 0);
    load_stage(1, 1);

    int lrow = lane & 15, lhi = lane >> 4;
    for (int kt = 0; kt < NKT; ++kt) {
        asm volatile("cp.async.wait_group 1;" ::: "memory");   // group kt done (kt+1 may pend)
        __syncthreads();                                       // all done with compute kt-1
        int nb = kt + 2;
        if (nb < NKT) load_stage(nb, nb % 3);
        else asm volatile("cp.async.commit_group;" ::: "memory");

        uint32_t stA = dbase + (kt % 3) * STG_BYTES;
        uint32_t stB = stA + 18432;
#pragma unroll
        for (int h = 0; h < 4; h++) {
            uint32_t a[2][4], b[8][2];
#pragma unroll
            for (int i = 0; i < 2; i++)
                ldsm4(a[i], stA + (wm * 32 + i * 16 + lrow) * 144 + (h * 2 + lhi) * 16);
#pragma unroll
            for (int jp = 0; jp < 4; jp++) {
                uint32_t t4[4];
                ldsm4(t4, stB + (wn * 64 + jp * 16 + lrow) * 144 + (h * 2 + lhi) * 16);
                b[2 * jp][0] = t4[0];  b[2 * jp][1] = t4[2];
                b[2 * jp + 1][0] = t4[1]; b[2 * jp + 1][1] = t4[3];
            }
#pragma unroll
            for (int i = 0; i < 2; i++)
#pragma unroll
                for (int j = 0; j < 8; j++)
                    mma_fp8(acc[i][j], a[i], b[j]);
        }
    }
    __syncthreads();   // before aliasing stage smem for epilogue

    float* sEpi = (float*)dsm + warp * 1088;
    int row0 = lane >> 2, col0 = 2 * (lane & 3);

#pragma unroll
    for (int i = 0; i < 2; i++) {
#pragma unroll
        for (int j = 0; j < 8; j++) {
            sEpi[row0 * 68 + 8 * j + col0]           = acc[i][j][0];
            sEpi[row0 * 68 + 8 * j + col0 + 1]       = acc[i][j][1];
            sEpi[(row0 + 8) * 68 + 8 * j + col0]     = acc[i][j][2];
            sEpi[(row0 + 8) * 68 + 8 * j + col0 + 1] = acc[i][j][3];
        }
        __syncwarp();
        int growb = m0 + wm * 32 + i * 16;
        int gcolb = n0 + wn * 64;
#pragma unroll
        for (int e = 0; e < 32; e++) {
            int idx = e * 32 + lane;
            int rr, cc;
            if (MODE == 3) { cc = idx >> 4; rr = idx & 15; }
            else           { rr = idx >> 6; cc = idx & 63; }
            float v = sEpi[rr * 68 + cc];
            int grow = growb + rr, gcol = gcolb + cc;
            if (MODE == 0) {
                g_qkv[(size_t)grow * Ncols + gcol] = q1(v);
            } else if (MODE == 2) {
                g_m1[(size_t)grow * Ncols + gcol] = q1(v + bias[gcol]);
            } else if (MODE == 1) {
                int win = grow >> 6, t = grow & 63;
                int b = win / 49, wi = win % 49;
                int gi = wi / 7, gj = wi % 7;
                int si = t >> 3, sj = t & 7;
                int h = si * GG + gi, wp = sj * GG + gj;
                size_t ridx = ((size_t)b * NS + h * WW_ + wp) * CC_ + gcol;
                g_x1[ridx] = g_xT[ridx] + gamma[gcol] * (v + bias[gcol]);
            } else {
                int b = grow / NS, n = grow % NS;
                float ov = g_x1[(size_t)grow * CC_ + gcol]
                         + gamma[gcol] * (v + bias[gcol]);
                outp[((size_t)b * CC_ + gcol) * NS + n] = ov;
            }
        }
        __syncwarp();
    }
}

// ---------------- K4: FP8 attention, one block per (window, head), 4 warps ----------------
// Q,K,Vt,P,O tiles in 80B-stride smem (conflict-free ldmatrix); softmax in registers.
__global__ void __launch_bounds__(128) k_attn() {
    int win = blockIdx.x, head = blockIdx.y;
    __shared__ __align__(16) uint8_t sQ[64 * 80], sK[64 * 80], sVt[64 * 80],
                                     sP[64 * 80], sO[64 * 80];
    int tid = threadIdx.x, lane = tid & 31, warp = tid >> 5;
    size_t base = (size_t)win * 64 * 1152 + head * 48;

    // Q, K: 64 rows x 3 x 16B
    for (int li = tid; li < 192; li += 128) {
        int t = li / 3, c = (li % 3) * 16;
        *(uint4*)&sQ[t * 80 + c] = *(const uint4*)&g_qkv[base + (size_t)t * 1152 + c];
        *(uint4*)&sK[t * 80 + c] = *(const uint4*)&g_qkv[base + (size_t)t * 1152 + 384 + c];
    }
    if (tid < 64) {   // zero-pad d 48..63
        *(uint4*)&sQ[tid * 80 + 48] = make_uint4(0u, 0u, 0u, 0u);
        *(uint4*)&sK[tid * 80 + 48] = make_uint4(0u, 0u, 0u, 0u);
    }
    // V transposed: sVt[d][t]
    for (int li = tid; li < 768; li += 128) {
        int t = li / 12, dc = li % 12;
        uint32_t v = *(const uint32_t*)&g_qkv[base + (size_t)t * 1152 + 768 + dc * 4];
        sVt[(dc * 4 + 0) * 80 + t] = (uint8_t)v;
        sVt[(dc * 4 + 1) * 80 + t] = (uint8_t)(v >> 8);
        sVt[(dc * 4 + 2) * 80 + t] = (uint8_t)(v >> 16);
        sVt[(dc * 4 + 3) * 80 + t] = (uint8_t)(v >> 24);
    }
    if (tid < 64) {   // zero sVt rows 48..63
        int r = 48 + (tid >> 2), c = (tid & 3) * 16;
        *(uint4*)&sVt[r * 80 + c] = make_uint4(0u, 0u, 0u, 0u);
    }
    __syncthreads();

    uint32_t aQ = sptr(sQ), aK = sptr(sK), aV = sptr(sVt), aP = sptr(sP);
    int m0 = warp * 16;
    int lrow = lane & 15, lhi = lane >> 4;

    // S = Q @ K^T (k = 64 padded dims)
    float accS[8][4];
#pragma unroll
    for (int j = 0; j < 8; j++)
#pragma unroll
        for (int q = 0; q < 4; q++) accS[j][q] = 0.0f;
#pragma unroll
    for (int h = 0; h < 2; h++) {
        uint32_t a[4];
        ldsm4(a, aQ + (m0 + lrow) * 80 + (h * 2 + lhi) * 16);
#pragma unroll
        for (int jp = 0; jp < 4; jp++) {
            uint32_t t4[4];
            ldsm4(t4, aK + (jp * 16 + lrow) * 80 + (h * 2 + lhi) * 16);
            uint32_t b0[2] = { t4[0], t4[2] }, b1[2] = { t4[1], t4[3] };
            mma_fp8(accS[2 * jp], a, b0);
            mma_fp8(accS[2 * jp + 1], a, b1);
        }
    }

    // softmax in registers: row_lo = m0+lane/4 (c0,c1), row_hi = +8 (c2,c3)
    const float scale = 0.14433756729740643f;   // 48^-0.5
    float mx0 = -1e30f, mx1 = -1e30f;
#pragma unroll
    for (int j = 0; j < 8; j++) {
        accS[j][0] *= scale; accS[j][1] *= scale; accS[j][2] *= scale; accS[j][3] *= scale;
        mx0 = fmaxf(mx0, fmaxf(accS[j][0], accS[j][1]));
        mx1 = fmaxf(mx1, fmaxf(accS[j][2], accS[j][3]));
    }
    mx0 = fmaxf(mx0, __shfl_xor_sync(0xffffffffu, mx0, 1));
    mx0 = fmaxf(mx0, __shfl_xor_sync(0xffffffffu, mx0, 2));
    mx1 = fmaxf(mx1, __shfl_xor_sync(0xffffffffu, mx1, 1));
    mx1 = fmaxf(mx1, __shfl_xor_sync(0xffffffffu, mx1, 2));
    float s0 = 0.0f, s1 = 0.0f;
#pragma unroll
    for (int j = 0; j < 8; j++) {
        accS[j][0] = __expf(accS[j][0] - mx0); s0 += accS[j][0];
        accS[j][1] = __expf(accS[j][1] - mx0); s0 += accS[j][1];
        accS[j][2] = __expf(accS[j][2] - mx1); s1 += accS[j][2];
        accS[j][3] = __expf(accS[j][3] - mx1); s1 += accS[j][3];
    }
    s0 += __shfl_xor_sync(0xffffffffu, s0, 1); s0 += __shfl_xor_sync(0xffffffffu, s0, 2);
    s1 += __shfl_xor_sync(0xffffffffu, s1, 1); s1 += __shfl_xor_sync(0xffffffffu, s1, 2);
    float inv0 = 1.0f / s0, inv1 = 1.0f / s1;

    int row_lo = m0 + (lane >> 2), row_hi = row_lo + 8;
    int colp = 2 * (lane & 3);
#pragma unroll
    for (int j = 0; j < 8; j++) {
        uint16_t p0 = (uint16_t)q1(accS[j][0] * inv0) | ((uint16_t)q1(accS[j][1] * inv0) << 8);
        uint16_t p1 = (uint16_t)q1(accS[j][2] * inv1) | ((uint16_t)q1(accS[j][3] * inv1) << 8);
        *(uint16_t*)&sP[row_lo * 80 + j * 8 + colp] = p0;
        *(uint16_t*)&sP[row_hi * 80 + j * 8 + colp] = p1;
    }
    __syncwarp();   // sP rows m0..m0+15 written by this warp; ldsm below reads only those

    // O = P @ V^T  (k = 64 tokens, n = 48 dims)
    float accO[6][4];
#pragma unroll
    for (int j = 0; j < 6; j++)
#pragma unroll
        for (int q = 0; q < 4; q++) accO[j][q] = 0.0f;
#pragma unroll
    for (int h = 0; h < 2; h++) {
        uint32_t a[4];
        ldsm4(a, aP + (m0 + lrow) * 80 + (h * 2 + lhi) * 16);
#pragma unroll
        for (int jp = 0; jp < 3; jp++) {
            uint32_t t4[4];
            ldsm4(t4, aV + (jp * 16 + lrow) * 80 + (h * 2 + lhi) * 16);
            uint32_t b0[2] = { t4[0], t4[2] }, b1[2] = { t4[1], t4[3] };
            mma_fp8(accO[2 * jp], a, b0);
            mma_fp8(accO[2 * jp + 1], a, b1);
        }
    }
#pragma unroll
    for (int j = 0; j < 6; j++) {
        uint16_t p0 = (uint16_t)q1(accO[j][0]) | ((uint16_t)q1(accO[j][1]) << 8);
        uint16_t p1 = (uint16_t)q1(accO[j][2]) | ((uint16_t)q1(accO[j][3]) << 8);
        *(uint16_t*)&sO[row_lo * 80 + j * 8 + colp] = p0;
        *(uint16_t*)&sO[row_hi * 80 + j * 8 + colp] = p1;
    }
    __syncthreads();

    uint8_t* dst = g_o + (size_t)win * 64 * 384 + head * 48;
    for (int li = tid; li < 192; li += 128) {
        int t = li / 3, c = (li % 3) * 16;
        *(uint4*)&dst[(size_t)t * 384 + c] = *(uint4*)&sO[t * 80 + c];
    }
}

// ---------------- K8: depthwise 3x3 conv + bias + exact GELU (4 rows/block, fp8 in/out) ----------------
__global__ void __launch_bounds__(256) k_dwconv(const float* __restrict__ wgt,
                                                const float* __restrict__ bias) {
    __shared__ __nv_bfloat16 s[6 * 58 * 64];
    int b = blockIdx.y, h0 = blockIdx.x * 4;   // grid (14, 32)
    int tid = threadIdx.x;
    int c = tid & 63, sub = tid >> 6;

    for (int cc = 0; cc < HID; cc += 64) {
        __syncthreads();
        for (int li = tid; li < 6 * 58 * 8; li += 256) {
            int hr = li / 464;
            int rem = li % 464;
            int wi = rem >> 3;
            int grp = (rem & 7) * 8;
            int hh = h0 - 1 + hr, ww = wi - 1;
            uint2 v8 = make_uint2(0u, 0u);
            if (hh >= 0 && hh < HH_ && ww >= 0 && ww < WW_)
                v8 = *(const uint2*)&g_m1[((size_t)b * NS + hh * WW_ + ww) * HID + cc + grp];
            uint2 lo = d4_bf16(v8.x), hi = d4_bf16(v8.y);
            *(uint4*)&s[(hr * 58 + wi) * 64 + grp] = make_uint4(lo.x, lo.y, hi.x, hi.y);
        }
        __syncthreads();

        int ch = cc + c;
        float w9[9];
#pragma unroll
        for (int i = 0; i < 9; i++) w9[i] = wgt[ch * 9 + i];
        float bv = bias[ch];
        int h = h0 + sub;
        for (int w0 = 0; w0 < WW_; w0++) {
            float acc = bv;
#pragma unroll
            for (int dy = 0; dy < 3; dy++)
#pragma unroll
                for (int dx = 0; dx < 3; dx++)
                    acc += __bfloat162float(s[((sub + dy) * 58 + w0 + dx) * 64 + c]) * w9[dy * 3 + dx];
            float gl = 0.5f * acc * (1.0f + erff(acc * 0.70710678118f));
            g_mg[((size_t)b * NS + h * WW_ + w0) * HID + ch] = q1(gl);
        }
    }
}

// ---------------- launch ----------------
extern "C" void kernel_launch(void* const* d_in, const int* in_sizes, int n_in,
                              void* d_out, int out_size) {
    (void)in_sizes; (void)n_in; (void)out_size;
    const float* x      = (const float*)d_in[0];
    const float* ln1_g  = (const float*)d_in[1];
    const float* ln1_b  = (const float*)d_in[2];
    const float* qkv_w  = (const float*)d_in[3];
    const float* proj_w = (const float*)d_in[4];
    const float* proj_b = (const float*)d_in[5];
    const float* ln2_g  = (const float*)d_in[6];
    const float* ln2_b  = (const float*)d_in[7];
    const float* fc1_w  = (const float*)d_in[8];
    const float* fc1_b  = (const float*)d_in[9];
    const float* dw_w   = (const float*)d_in[10];
    const float* dw_b   = (const float*)d_in[11];
    const float* fc2_w  = (const float*)d_in[12];
    const float* fc2_b  = (const float*)d_in[13];
    const float* gamma1 = (const float*)d_in[14];
    const float* gamma2 = (const float*)d_in[15];
    float* out = (float*)d_out;

    // idempotent, deterministic, capture-safe
    cudaFuncSetAttribute(k_tln,     cudaFuncAttributeMaxDynamicSharedMemorySize, TLN_SMEM);
    cudaFuncSetAttribute(k_gemm<0>, cudaFuncAttributeMaxDynamicSharedMemorySize, GEMM_DSMEM);
    cudaFuncSetAttribute(k_gemm<1>, cudaFuncAttributeMaxDynamicSharedMemorySize, GEMM_DSMEM);
    cudaFuncSetAttribute(k_gemm<2>, cudaFuncAttributeMaxDynamicSharedMemorySize, GEMM_DSMEM);
    cudaFuncSetAttribute(k_gemm<3>, cudaFuncAttributeMaxDynamicSharedMemorySize, GEMM_DSMEM);

    k_wprep_all<<<1728, dim3(32, 8)>>>(qkv_w, proj_w, fc1_w, fc2_w);
    k_tln<<<dim3(NS / 32, BB), 256, TLN_SMEM>>>(x, ln1_g, ln1_b);
    k_gemm<0><<<dim3(1152 / 128, MR / 128), 256, GEMM_DSMEM>>>(nullptr, nullptr, nullptr);
    k_attn<<<dim3(NWIN, NHEADS), 128>>>();
    k_gemm<1><<<dim3(384 / 128, MR / 128), 256, GEMM_DSMEM>>>(proj_b, gamma1, nullptr);
    k_layernorm2<<<MR, 128>>>(ln2_g, ln2_b);
    k_gemm<2><<<dim3(1536 / 128, MR / 128), 256, GEMM_DSMEM>>>(fc1_b, nullptr, nullptr);
    k_dwconv<<<dim3(14, BB), 256>>>(dw_w, dw_b);
    k_gemm<3><<<dim3(384 / 128, MR / 128), 256, GEMM_DSMEM>>>(fc2_b, gamma2, out);
}